// round 1
// baseline (speedup 1.0000x reference)
#include <cuda_runtime.h>

// ---------------------------------------------------------------------------
// WindowAttention: x(2048,512,7,7) -> out(2048,512,7,7)
// bs=2048, c=512, ws=7, N=49, H=16, hd=32, n_windows=64, M=bs*N=100352
// Pipeline:
//   prep_w   : permute qkv_w/qkv_b columns (hd,heads,3)->(s,h,d), pre-scale q
//   prep_bm  : g_bm[w][h][n][m] = bias_table[relpos_idx(n,m)][h] + mask[w][n][m]
//   gemm_qkv : g_qkv[M,1536] = gather(x) @ g_w + g_bvec   (row-major, coalesced)
//   attn     : per-(b,h) block: S=QK^T + bm, softmax, O=PV -> g_ao[M,512]
//   gemm_proj: out = transpose(g_ao @ proj_w + proj_b)    (b,c,n) layout
// ---------------------------------------------------------------------------

#define SCALE_Q 0.17677669529663687f   // 32^-0.5

// Scratch (device globals; allocation inside kernel_launch is forbidden)
__device__ float g_w[512 * 1536];          //   3.0 MB  permuted qkv weight
__device__ float g_bvec[1536];             //           permuted qkv bias
__device__ float g_bm[64 * 16 * 2401];     //   9.8 MB  fused bias+mask
__device__ float g_qkv[154140672];         // 616.6 MB  M x 1536
__device__ float g_ao[51380224];           // 205.5 MB  M x 512

// ---------------------------------------------------------------------------
__global__ void prep_w_kernel(const float* __restrict__ qw,
                              const float* __restrict__ qb) {
    int t = blockIdx.x * blockDim.x + threadIdx.x;
    if (t < 512 * 1536) {
        int k  = t / 1536;
        int jn = t - k * 1536;           // jn = s*512 + h*32 + d
        int s  = jn >> 9;
        int r  = jn & 511;
        int h  = r >> 5;
        int d  = r & 31;
        int jo = d * 48 + h * 3 + s;     // source column in (hd, heads, 3) packing
        float v = qw[k * 1536 + jo];
        if (s == 0) v *= SCALE_Q;
        g_w[t] = v;
    }
    if (t < 1536) {
        int s = t >> 9;
        int r = t & 511;
        int h = r >> 5;
        int d = r & 31;
        int jo = d * 48 + h * 3 + s;
        float v = qb[jo];
        if (s == 0) v *= SCALE_Q;
        g_bvec[t] = v;
    }
}

// ---------------------------------------------------------------------------
__global__ void prep_bm_kernel(const float* __restrict__ mask,
                               const float* __restrict__ table) {
    int t = blockIdx.x * blockDim.x + threadIdx.x;
    if (t >= 64 * 16 * 2401) return;
    int w = t / (16 * 2401);
    int r = t - w * (16 * 2401);
    int h = r / 2401;
    int e = r - h * 2401;
    int n = e / 49;
    int m = e - n * 49;
    // reference index formula: idx = (di+6)*6 + (dj+6), di=ni-mi, dj=nj-mj
    int di = n / 7 - m / 7 + 6;
    int dj = (n % 7) - (m % 7) + 6;
    int idx = di * 6 + dj;
    g_bm[t] = table[idx * 16 + h] + mask[w * 2401 + e];
}

// ---------------------------------------------------------------------------
// QKV GEMM: C[M,1536] = A[M,512] @ g_w + g_bvec
// A gathered from x: A[row=(b*49+n)][k=ch] = x[(b*512+ch)*49 + n]
// 128x128x16 tile, 256 threads, 8x8 microtile.
__global__ __launch_bounds__(256) void gemm_qkv_kernel(const float* __restrict__ x) {
    __shared__ float As[16][128];
    __shared__ float Bs[16][128];
    const int tid = threadIdx.x;
    const int tx = tid & 15, ty = tid >> 4;
    const int m0 = blockIdx.y << 7;
    const int n0 = blockIdx.x << 7;

    // Hoisted A-gather addressing (r, kk fixed per thread across k-chunks)
    int a_goff[8], a_soff[8];
#pragma unroll
    for (int i = 0; i < 8; i++) {
        int idx = tid + (i << 8);        // 0..2047
        int kk  = idx >> 7;
        int r   = idx & 127;
        int row = m0 + r;
        int b   = row / 49;
        int n   = row - b * 49;
        a_goff[i] = b * 25088 + kk * 49 + n;   // + (k0)*49 at use
        a_soff[i] = kk * 128 + r;
    }
    int b_goff[2], b_soff[2];
#pragma unroll
    for (int i = 0; i < 2; i++) {
        int idx = tid + (i << 8);        // 0..511 (float4 units)
        int kk  = idx >> 5;
        int c4  = idx & 31;
        b_goff[i] = kk * 1536 + n0 + (c4 << 2);
        b_soff[i] = kk * 128 + (c4 << 2);
    }

    float acc[8][8] = {};
    float* Asf = &As[0][0];
    float* Bsf = &Bs[0][0];

    for (int k0 = 0; k0 < 512; k0 += 16) {
#pragma unroll
        for (int i = 0; i < 8; i++)
            Asf[a_soff[i]] = x[a_goff[i] + k0 * 49];
#pragma unroll
        for (int i = 0; i < 2; i++)
            *(float4*)(Bsf + b_soff[i]) = *(const float4*)(g_w + k0 * 1536 + b_goff[i]);
        __syncthreads();
#pragma unroll
        for (int kk = 0; kk < 16; kk++) {
            float a[8], bb[8];
            *(float4*)&a[0]  = *(float4*)&As[kk][ty * 8];
            *(float4*)&a[4]  = *(float4*)&As[kk][ty * 8 + 4];
            *(float4*)&bb[0] = *(float4*)&Bs[kk][tx * 8];
            *(float4*)&bb[4] = *(float4*)&Bs[kk][tx * 8 + 4];
#pragma unroll
            for (int i = 0; i < 8; i++)
#pragma unroll
                for (int j = 0; j < 8; j++)
                    acc[i][j] = fmaf(a[i], bb[j], acc[i][j]);
        }
        __syncthreads();
    }
#pragma unroll
    for (int i = 0; i < 8; i++) {
        int row = m0 + ty * 8 + i;
        float* crow = g_qkv + (long)row * 1536 + n0 + tx * 8;
#pragma unroll
        for (int j = 0; j < 8; j += 4) {
            int col = n0 + tx * 8 + j;
            float4 v;
            v.x = acc[i][j + 0] + g_bvec[col + 0];
            v.y = acc[i][j + 1] + g_bvec[col + 1];
            v.z = acc[i][j + 2] + g_bvec[col + 2];
            v.w = acc[i][j + 3] + g_bvec[col + 3];
            *(float4*)(crow + j) = v;
        }
    }
}

// ---------------------------------------------------------------------------
// Attention: one block per (b, h). Q/K/V tiles are 49x32 fp32 in smem.
__global__ __launch_bounds__(128) void attn_kernel() {
    const int h = blockIdx.x;           // 0..15
    const int b = blockIdx.y;           // 0..2047
    const int w = b & 63;
    const int tid = threadIdx.x;

    __shared__ float sq[49][33];
    __shared__ float sk[49][33];
    __shared__ float sv[49][33];
    __shared__ float sS[49][50];
    __shared__ float sinv[49];

    const float* base = g_qkv + (long)b * 49 * 1536 + h * 32;
    for (int t = tid; t < 392; t += 128) {         // 49 rows x 8 float4
        int n  = t >> 3;
        int d  = (t & 7) << 2;
        const float* rp = base + n * 1536 + d;
        float4 q4 = *(const float4*)(rp);
        float4 k4 = *(const float4*)(rp + 512);
        float4 v4 = *(const float4*)(rp + 1024);
        sq[n][d] = q4.x; sq[n][d + 1] = q4.y; sq[n][d + 2] = q4.z; sq[n][d + 3] = q4.w;
        sk[n][d] = k4.x; sk[n][d + 1] = k4.y; sk[n][d + 2] = k4.z; sk[n][d + 3] = k4.w;
        sv[n][d] = v4.x; sv[n][d + 1] = v4.y; sv[n][d + 2] = v4.z; sv[n][d + 3] = v4.w;
    }
    __syncthreads();

    const float* bm = g_bm + (w * 16 + h) * 2401;
    for (int e = tid; e < 2401; e += 128) {
        int i = e / 49;
        int j = e - i * 49;
        float acc = bm[e];
#pragma unroll
        for (int d = 0; d < 32; d++)
            acc = fmaf(sq[i][d], sk[j][d], acc);
        sS[i][j] = acc;
    }
    __syncthreads();

    if (tid < 49) {
        float mx = -1e30f;
#pragma unroll
        for (int j = 0; j < 49; j++) mx = fmaxf(mx, sS[tid][j]);
        float s = 0.f;
#pragma unroll
        for (int j = 0; j < 49; j++) {
            float p = __expf(sS[tid][j] - mx);
            sS[tid][j] = p;
            s += p;
        }
        sinv[tid] = 1.0f / s;
    }
    __syncthreads();

    float* ob = g_ao + (long)b * 49 * 512 + h * 32;
    for (int e = tid; e < 1568; e += 128) {        // 49 x 32
        int i = e >> 5;
        int d = e & 31;
        float acc = 0.f;
#pragma unroll
        for (int j = 0; j < 49; j++)
            acc = fmaf(sS[i][j], sv[j][d], acc);
        ob[i * 512 + d] = acc * sinv[i];
    }
}

// ---------------------------------------------------------------------------
// Proj GEMM: Y[M,512] = g_ao @ proj_w + proj_b, stored as out[(b*512+ch)*49+n]
__global__ __launch_bounds__(256) void gemm_proj_kernel(const float* __restrict__ pw,
                                                        const float* __restrict__ pb,
                                                        float* __restrict__ out) {
    __shared__ float As[16][128];
    __shared__ float Bs[16][128];
    __shared__ float stage[128][33];
    const int tid = threadIdx.x;
    const int tx = tid & 15, ty = tid >> 4;
    const int m0 = blockIdx.y << 7;
    const int n0 = blockIdx.x << 7;

    float acc[8][8] = {};
    float* Asf = &As[0][0];
    float* Bsf = &Bs[0][0];

    for (int k0 = 0; k0 < 512; k0 += 16) {
#pragma unroll
        for (int i = 0; i < 2; i++) {
            int idx = tid + (i << 8);            // 0..511 (float4 units)
            int r   = idx >> 2;
            int k4  = (idx & 3) << 2;
            float4 v = *(const float4*)(g_ao + (long)(m0 + r) * 512 + k0 + k4);
            int so = k4 * 128 + r;
            Asf[so] = v.x; Asf[so + 128] = v.y; Asf[so + 256] = v.z; Asf[so + 384] = v.w;
        }
#pragma unroll
        for (int i = 0; i < 2; i++) {
            int idx = tid + (i << 8);
            int kk  = idx >> 5;
            int c4  = (idx & 31) << 2;
            *(float4*)(Bsf + kk * 128 + c4) =
                *(const float4*)(pw + (k0 + kk) * 512 + n0 + c4);
        }
        __syncthreads();
#pragma unroll
        for (int kk = 0; kk < 16; kk++) {
            float a[8], bb[8];
            *(float4*)&a[0]  = *(float4*)&As[kk][ty * 8];
            *(float4*)&a[4]  = *(float4*)&As[kk][ty * 8 + 4];
            *(float4*)&bb[0] = *(float4*)&Bs[kk][tx * 8];
            *(float4*)&bb[4] = *(float4*)&Bs[kk][tx * 8 + 4];
#pragma unroll
            for (int i = 0; i < 8; i++)
#pragma unroll
                for (int j = 0; j < 8; j++)
                    acc[i][j] = fmaf(a[i], bb[j], acc[i][j]);
        }
        __syncthreads();
    }

    // Transposed store via smem staging: 4 chunks of 32 columns
    for (int c0 = 0; c0 < 128; c0 += 32) {
        __syncthreads();
        if (tx >= (c0 >> 3) && tx < (c0 >> 3) + 4) {
#pragma unroll
            for (int i = 0; i < 8; i++)
#pragma unroll
                for (int j = 0; j < 8; j++) {
                    int cc = tx * 8 + j - c0;
                    stage[ty * 8 + i][cc] = acc[i][j] + pb[n0 + c0 + cc];
                }
        }
        __syncthreads();
        for (int t = tid; t < 4096; t += 256) {
            int r  = t & 127;
            int cc = t >> 7;
            int row = m0 + r;
            int b = row / 49;
            int n = row - b * 49;
            int ch = n0 + c0 + cc;
            out[(long)(b * 512 + ch) * 49 + n] = stage[r][cc];
        }
    }
}

// ---------------------------------------------------------------------------
extern "C" void kernel_launch(void* const* d_in, const int* in_sizes, int n_in,
                              void* d_out, int out_size) {
    const float *x = nullptr, *mask = nullptr, *table = nullptr;
    const float *qw = nullptr, *qb = nullptr, *pw = nullptr, *pb = nullptr;
    for (int i = 0; i < n_in; i++) {
        const float* p = (const float*)d_in[i];
        switch (in_sizes[i]) {
            case 51380224: x = p; break;      // x (2048,512,7,7)
            case 153664:   mask = p; break;   // mask (64,49,49)
            case 2704:     table = p; break;  // bias_table (169,16)
            case 786432:   qw = p; break;     // qkv_w (512,1536)
            case 1536:     qb = p; break;     // qkv_b
            case 262144:   pw = p; break;     // proj_w (512,512)
            case 512:      pb = p; break;     // proj_b
        }
    }
    float* out = (float*)d_out;

    prep_w_kernel<<<(512 * 1536 + 255) / 256, 256>>>(qw, qb);
    prep_bm_kernel<<<(64 * 16 * 2401 + 255) / 256, 256>>>(mask, table);
    gemm_qkv_kernel<<<dim3(12, 784), 256>>>(x);
    attn_kernel<<<dim3(16, 2048), 128>>>();
    gemm_proj_kernel<<<dim3(4, 784), 256>>>(pw, pb, out);
}

// round 2
// speedup vs baseline: 1.8777x; 1.8777x over previous
#include <cuda_runtime.h>
#include <cstdint>

// ---------------------------------------------------------------------------
// WindowAttention: x(2048,512,7,7) -> out(2048,512,7,7)
// bs=2048, c=512, ws=7, N=49, H=16, hd=32, n_windows=64, M=bs*N=100352
// Round 2: tf32 mma.sync tensor-core GEMMs (cp.async double-buffered),
//          rna-prerounded operands, fp32 attention unchanged.
// ---------------------------------------------------------------------------

#define SCALE_Q 0.17677669529663687f   // 32^-0.5

__device__ float g_w[512 * 1536];          //   3.0 MB  permuted+rounded qkv weight
__device__ float g_pw[512 * 512];          //   1.0 MB  rounded proj weight
__device__ float g_bvec[1536];             //           permuted qkv bias (exact)
__device__ float g_bm[64 * 16 * 2401];     //   9.8 MB  fused bias+mask
__device__ float g_xr[51380224];           // 205.5 MB  tf32-rounded x
__device__ float g_qkv[154140672];         // 616.6 MB  M x 1536
__device__ float g_ao[51380224];           // 205.5 MB  M x 512 (tf32-rounded)

__device__ __forceinline__ float rna_tf32(float x) {
    uint32_t u;
    asm("cvt.rna.tf32.f32 %0, %1;" : "=r"(u) : "f"(x));
    return __uint_as_float(u);
}
__device__ __forceinline__ void cp_async4(uint32_t dst, const void* src) {
    asm volatile("cp.async.ca.shared.global [%0], [%1], 4;" :: "r"(dst), "l"(src));
}
__device__ __forceinline__ void cp_async16(uint32_t dst, const void* src) {
    asm volatile("cp.async.cg.shared.global [%0], [%1], 16;" :: "r"(dst), "l"(src));
}
#define CP_COMMIT() asm volatile("cp.async.commit_group;")
#define CP_WAIT1()  asm volatile("cp.async.wait_group 1;")

#define MMA_TF32(c, a, b)                                                     \
    asm volatile("mma.sync.aligned.m16n8k8.row.col.f32.tf32.tf32.f32 "        \
        "{%0,%1,%2,%3}, {%4,%5,%6,%7}, {%8,%9}, {%0,%1,%2,%3};"               \
        : "+f"((c)[0]), "+f"((c)[1]), "+f"((c)[2]), "+f"((c)[3])              \
        : "r"((a)[0]), "r"((a)[1]), "r"((a)[2]), "r"((a)[3]),                 \
          "r"((b)[0]), "r"((b)[1]))

// ---------------------------------------------------------------------------
__global__ void prep_w_kernel(const float* __restrict__ qw,
                              const float* __restrict__ qb,
                              const float* __restrict__ pw) {
    int t = blockIdx.x * blockDim.x + threadIdx.x;
    if (t < 512 * 1536) {
        int k  = t / 1536;
        int jn = t - k * 1536;           // jn = s*512 + h*32 + d
        int s  = jn >> 9;
        int r  = jn & 511;
        int h  = r >> 5;
        int d  = r & 31;
        int jo = d * 48 + h * 3 + s;     // source column in (hd, heads, 3) packing
        float v = qw[k * 1536 + jo];
        if (s == 0) v *= SCALE_Q;
        g_w[t] = rna_tf32(v);
    }
    if (t < 512 * 512) g_pw[t] = rna_tf32(pw[t]);
    if (t < 1536) {
        int s = t >> 9;
        int r = t & 511;
        int h = r >> 5;
        int d = r & 31;
        int jo = d * 48 + h * 3 + s;
        float v = qb[jo];
        if (s == 0) v *= SCALE_Q;
        g_bvec[t] = v;
    }
}

__global__ void prep_x_kernel(const float* __restrict__ x) {
    int t = blockIdx.x * blockDim.x + threadIdx.x;
    if (t < 51380224) g_xr[t] = rna_tf32(x[t]);
}

__global__ void prep_bm_kernel(const float* __restrict__ mask,
                               const float* __restrict__ table) {
    int t = blockIdx.x * blockDim.x + threadIdx.x;
    if (t >= 64 * 16 * 2401) return;
    int w = t / (16 * 2401);
    int r = t - w * (16 * 2401);
    int h = r / 2401;
    int e = r - h * 2401;
    int n = e / 49;
    int m = e - n * 49;
    int di = n / 7 - m / 7 + 6;
    int dj = (n % 7) - (m % 7) + 6;
    int idx = di * 6 + dj;
    g_bm[t] = table[idx * 16 + h] + mask[w * 2401 + e];
}

// ---------------------------------------------------------------------------
// QKV GEMM (tf32 TC): C[M,1536] = gather(g_xr) @ g_w + g_bvec
// block 128x128, K-chunk 16, double-buffered cp.async; 8 warps, warp 64x32.
// smem: As[2][128*20] (layout [m][20]) + Bs[2][16*136] (layout [k][136])
__global__ __launch_bounds__(256) void gemm_qkv_tc() {
    __shared__ __align__(16) float sm[9472];   // 2*2560 + 2*2176 floats
    const int tid  = threadIdx.x;
    const int lane = tid & 31, warp = tid >> 5;
    const int wm = warp >> 2, wn = warp & 3;
    const int m0 = blockIdx.y << 7;
    const int n0 = blockIdx.x << 7;

    uint32_t As_u = (uint32_t)__cvta_generic_to_shared(sm);
    uint32_t Bs_u = As_u + 5120 * 4;

    // A gather (from g_xr: A[m][k] = x[b*25088 + k*49 + n])
    const int m_l = tid & 127;
    const int kb  = tid >> 7;                  // 0 or 1
    int row = m0 + m_l;
    int ab  = row / 49;
    int an  = row - ab * 49;
    const float* a_src0 = g_xr + ab * 25088 + an + kb * 49;
    const uint32_t a_dst0 = As_u + (m_l * 20 + kb) * 4;

    // B load
    const int bk  = tid >> 5;                  // 0..7
    const int bc4 = (tid & 31) * 4;
    const float* b_src0 = g_w + bk * 1536 + n0 + bc4;
    const uint32_t b_dst0 = Bs_u + (bk * 136 + bc4) * 4;

#define QKV_LOAD(kc, s)                                                        \
    {                                                                          \
        const float* ap = a_src0 + (kc) * 784;                                 \
        uint32_t ad = a_dst0 + (s) * 10240;                                    \
        _Pragma("unroll")                                                      \
        for (int i = 0; i < 8; i++) cp_async4(ad + i * 8, ap + i * 98);        \
        const float* bp = b_src0 + (kc) * 24576;                               \
        uint32_t bd = b_dst0 + (s) * 8704;                                     \
        _Pragma("unroll")                                                      \
        for (int i = 0; i < 2; i++) cp_async16(bd + i * 4352, bp + i * 12288); \
    }

    float acc[4][4][4] = {};
    const int aro = (wm * 64 + (lane >> 2)) * 20 + (lane & 3);
    const int bro = (lane & 3) * 136 + wn * 32 + (lane >> 2);

    QKV_LOAD(0, 0);
    CP_COMMIT();
    int buf = 0;
    for (int kc = 0; kc < 32; kc++) {
        if (kc < 31) QKV_LOAD(kc + 1, buf ^ 1);
        CP_COMMIT();
        CP_WAIT1();
        __syncthreads();
        const float* A = sm + buf * 2560;
        const float* B = sm + 5120 + buf * 2176;
#pragma unroll
        for (int ks = 0; ks < 2; ks++) {
            uint32_t af[4][4], bf[4][2];
#pragma unroll
            for (int tm = 0; tm < 4; tm++) {
                const float* p = A + aro + tm * 320 + ks * 8;
                af[tm][0] = __float_as_uint(p[0]);
                af[tm][1] = __float_as_uint(p[160]);
                af[tm][2] = __float_as_uint(p[4]);
                af[tm][3] = __float_as_uint(p[164]);
            }
#pragma unroll
            for (int tn = 0; tn < 4; tn++) {
                const float* p = B + ks * 1088 + bro + tn * 8;
                bf[tn][0] = __float_as_uint(p[0]);
                bf[tn][1] = __float_as_uint(p[544]);
            }
#pragma unroll
            for (int tm = 0; tm < 4; tm++)
#pragma unroll
                for (int tn = 0; tn < 4; tn++)
                    MMA_TF32(acc[tm][tn], af[tm], bf[tn]);
        }
        __syncthreads();
        buf ^= 1;
    }

#pragma unroll
    for (int tm = 0; tm < 4; tm++) {
        int r = m0 + wm * 64 + tm * 16 + (lane >> 2);
#pragma unroll
        for (int tn = 0; tn < 4; tn++) {
            int cidx = n0 + wn * 32 + tn * 8 + (lane & 3) * 2;
            float b0 = g_bvec[cidx], b1 = g_bvec[cidx + 1];
            float2 v0 = {acc[tm][tn][0] + b0, acc[tm][tn][1] + b1};
            float2 v1 = {acc[tm][tn][2] + b0, acc[tm][tn][3] + b1};
            *(float2*)(g_qkv + (long)r * 1536 + cidx)       = v0;
            *(float2*)(g_qkv + (long)(r + 8) * 1536 + cidx) = v1;
        }
    }
}

// ---------------------------------------------------------------------------
// Attention (fp32, unchanged except tf32-rounded output for the proj GEMM)
__global__ __launch_bounds__(128) void attn_kernel() {
    const int h = blockIdx.x;
    const int b = blockIdx.y;
    const int w = b & 63;
    const int tid = threadIdx.x;

    __shared__ float sq[49][33];
    __shared__ float sk[49][33];
    __shared__ float sv[49][33];
    __shared__ float sS[49][50];
    __shared__ float sinv[49];

    const float* base = g_qkv + (long)b * 49 * 1536 + h * 32;
    for (int t = tid; t < 392; t += 128) {
        int n  = t >> 3;
        int d  = (t & 7) << 2;
        const float* rp = base + n * 1536 + d;
        float4 q4 = *(const float4*)(rp);
        float4 k4 = *(const float4*)(rp + 512);
        float4 v4 = *(const float4*)(rp + 1024);
        sq[n][d] = q4.x; sq[n][d + 1] = q4.y; sq[n][d + 2] = q4.z; sq[n][d + 3] = q4.w;
        sk[n][d] = k4.x; sk[n][d + 1] = k4.y; sk[n][d + 2] = k4.z; sk[n][d + 3] = k4.w;
        sv[n][d] = v4.x; sv[n][d + 1] = v4.y; sv[n][d + 2] = v4.z; sv[n][d + 3] = v4.w;
    }
    __syncthreads();

    const float* bm = g_bm + (w * 16 + h) * 2401;
    for (int e = tid; e < 2401; e += 128) {
        int i = e / 49;
        int j = e - i * 49;
        float acc = bm[e];
#pragma unroll
        for (int d = 0; d < 32; d++)
            acc = fmaf(sq[i][d], sk[j][d], acc);
        sS[i][j] = acc;
    }
    __syncthreads();

    if (tid < 49) {
        float mx = -1e30f;
#pragma unroll
        for (int j = 0; j < 49; j++) mx = fmaxf(mx, sS[tid][j]);
        float s = 0.f;
#pragma unroll
        for (int j = 0; j < 49; j++) {
            float p = __expf(sS[tid][j] - mx);
            sS[tid][j] = p;
            s += p;
        }
        sinv[tid] = 1.0f / s;
    }
    __syncthreads();

    float* ob = g_ao + (long)b * 49 * 512 + h * 32;
    for (int e = tid; e < 1568; e += 128) {
        int i = e >> 5;
        int d = e & 31;
        float acc = 0.f;
#pragma unroll
        for (int j = 0; j < 49; j++)
            acc = fmaf(sS[i][j], sv[j][d], acc);
        ob[i * 512 + d] = rna_tf32(acc * sinv[i]);
    }
}

// ---------------------------------------------------------------------------
// Proj GEMM (tf32 TC): Y = g_ao @ g_pw + proj_b, stored transposed (b,c,n).
__global__ __launch_bounds__(256) void gemm_proj_tc(const float* __restrict__ pb,
                                                    float* __restrict__ out) {
    __shared__ __align__(16) float sm[9472];
    const int tid  = threadIdx.x;
    const int lane = tid & 31, warp = tid >> 5;
    const int wm = warp >> 2, wn = warp & 3;
    const int m0 = blockIdx.y << 7;
    const int n0 = blockIdx.x << 7;

    uint32_t As_u = (uint32_t)__cvta_generic_to_shared(sm);
    uint32_t Bs_u = As_u + 5120 * 4;

    // A: g_ao rows, float4 cp.async into [m][20]
    const int pm  = tid >> 2;                 // 0..63
    const int pk4 = (tid & 3) * 4;
    const float* a_src0 = g_ao + (long)(m0 + pm) * 512 + pk4;
    const uint32_t a_dst0 = As_u + (pm * 20 + pk4) * 4;

    const int bk  = tid >> 5;
    const int bc4 = (tid & 31) * 4;
    const float* b_src0 = g_pw + bk * 512 + n0 + bc4;
    const uint32_t b_dst0 = Bs_u + (bk * 136 + bc4) * 4;

#define PROJ_LOAD(kc, s)                                                       \
    {                                                                          \
        const float* ap = a_src0 + (kc) * 16;                                  \
        uint32_t ad = a_dst0 + (s) * 10240;                                    \
        _Pragma("unroll")                                                      \
        for (int i = 0; i < 2; i++) cp_async16(ad + i * 5120, ap + i * 32768); \
        const float* bp = b_src0 + (kc) * 8192;                                \
        uint32_t bd = b_dst0 + (s) * 8704;                                     \
        _Pragma("unroll")                                                      \
        for (int i = 0; i < 2; i++) cp_async16(bd + i * 4352, bp + i * 4096);  \
    }

    float acc[4][4][4] = {};
    const int aro = (wm * 64 + (lane >> 2)) * 20 + (lane & 3);
    const int bro = (lane & 3) * 136 + wn * 32 + (lane >> 2);

    PROJ_LOAD(0, 0);
    CP_COMMIT();
    int buf = 0;
    for (int kc = 0; kc < 32; kc++) {
        if (kc < 31) PROJ_LOAD(kc + 1, buf ^ 1);
        CP_COMMIT();
        CP_WAIT1();
        __syncthreads();
        const float* A = sm + buf * 2560;
        const float* B = sm + 5120 + buf * 2176;
#pragma unroll
        for (int ks = 0; ks < 2; ks++) {
            uint32_t af[4][4], bf[4][2];
#pragma unroll
            for (int tm = 0; tm < 4; tm++) {
                const float* p = A + aro + tm * 320 + ks * 8;
                af[tm][0] = __float_as_uint(p[0]);
                af[tm][1] = __float_as_uint(p[160]);
                af[tm][2] = __float_as_uint(p[4]);
                af[tm][3] = __float_as_uint(p[164]);
            }
#pragma unroll
            for (int tn = 0; tn < 4; tn++) {
                const float* p = B + ks * 1088 + bro + tn * 8;
                bf[tn][0] = __float_as_uint(p[0]);
                bf[tn][1] = __float_as_uint(p[544]);
            }
#pragma unroll
            for (int tm = 0; tm < 4; tm++)
#pragma unroll
                for (int tn = 0; tn < 4; tn++)
                    MMA_TF32(acc[tm][tn], af[tm], bf[tn]);
        }
        __syncthreads();
        buf ^= 1;
    }

    // Transposed epilogue via smem staging, two 64-column halves.
    float* stg = sm;                       // [128][66]
    const int r_l  = tid & 127;
    int rowg = m0 + r_l;
    int ob_b = rowg / 49;
    int ob_n = rowg - ob_b * 49;
    float* obase = out + (long)ob_b * 25088 + ob_n;
    const int ccb = tid >> 7;              // 0 or 1

    for (int half = 0; half < 2; half++) {
        __syncthreads();
        if ((wn >> 1) == half) {
#pragma unroll
            for (int tm = 0; tm < 4; tm++) {
                int rl = wm * 64 + tm * 16 + (lane >> 2);
#pragma unroll
                for (int tn = 0; tn < 4; tn++) {
                    int cl = (wn & 1) * 32 + tn * 8 + (lane & 3) * 2;
                    int cg = n0 + half * 64 + cl;
                    float b0 = pb[cg], b1 = pb[cg + 1];
                    stg[rl * 66 + cl]           = acc[tm][tn][0] + b0;
                    stg[rl * 66 + cl + 1]       = acc[tm][tn][1] + b1;
                    stg[(rl + 8) * 66 + cl]     = acc[tm][tn][2] + b0;
                    stg[(rl + 8) * 66 + cl + 1] = acc[tm][tn][3] + b1;
                }
            }
        }
        __syncthreads();
#pragma unroll
        for (int i = 0; i < 32; i++) {
            int cc = ccb + 2 * i;
            int ch = n0 + half * 64 + cc;
            obase[(long)ch * 49] = stg[r_l * 66 + cc];
        }
    }
}

// ---------------------------------------------------------------------------
extern "C" void kernel_launch(void* const* d_in, const int* in_sizes, int n_in,
                              void* d_out, int out_size) {
    const float *x = nullptr, *mask = nullptr, *table = nullptr;
    const float *qw = nullptr, *qb = nullptr, *pw = nullptr, *pb = nullptr;
    for (int i = 0; i < n_in; i++) {
        const float* p = (const float*)d_in[i];
        switch (in_sizes[i]) {
            case 51380224: x = p; break;
            case 153664:   mask = p; break;
            case 2704:     table = p; break;
            case 786432:   qw = p; break;
            case 1536:     qb = p; break;
            case 262144:   pw = p; break;
            case 512:      pb = p; break;
        }
    }
    float* out = (float*)d_out;

    prep_w_kernel<<<(512 * 1536 + 255) / 256, 256>>>(qw, qb, pw);
    prep_bm_kernel<<<(64 * 16 * 2401 + 255) / 256, 256>>>(mask, table);
    prep_x_kernel<<<(51380224 + 255) / 256, 256>>>(x);
    gemm_qkv_tc<<<dim3(12, 784), 256>>>();
    attn_kernel<<<dim3(16, 2048), 128>>>();
    gemm_proj_tc<<<dim3(4, 784), 256>>>(pb, out);
}

// round 3
// speedup vs baseline: 2.4181x; 1.2878x over previous
#include <cuda_runtime.h>
#include <cstdint>

// ---------------------------------------------------------------------------
// WindowAttention: x(2048,512,7,7) -> out(2048,512,7,7)
// bs=2048, c=512, ws=7, N=49, H=16, hd=32, n_windows=64, M=bs*N=100352
// Round 3: pre-transposed A + 3-stage cp.async (1 sync/chunk) GEMMs,
//          register-tiled fp32 attention.
// ---------------------------------------------------------------------------

#define SCALE_Q 0.17677669529663687f   // 32^-0.5

__device__ float g_w[512 * 1536];          //   3.0 MB  permuted+rounded qkv weight
__device__ float g_pw[512 * 512];          //   1.0 MB  rounded proj weight
__device__ float g_bvec[1536];             //           permuted qkv bias (exact)
__device__ float g_bm[64 * 16 * 2401];     //   9.8 MB  fused bias+mask
__device__ float g_xr[51380224];           // 205.5 MB  tf32-rounded, transposed x: [M][512]
__device__ float g_qkv[154140672];         // 616.6 MB  M x 1536
__device__ float g_ao[51380224];           // 205.5 MB  M x 512 (tf32-rounded)

__device__ __forceinline__ float rna_tf32(float x) {
    uint32_t u;
    asm("cvt.rna.tf32.f32 %0, %1;" : "=r"(u) : "f"(x));
    return __uint_as_float(u);
}
__device__ __forceinline__ void cp_async16(uint32_t dst, const void* src) {
    asm volatile("cp.async.cg.shared.global [%0], [%1], 16;" :: "r"(dst), "l"(src));
}
#define CP_COMMIT() asm volatile("cp.async.commit_group;")
#define CP_WAIT1()  asm volatile("cp.async.wait_group 1;")

#define MMA_TF32(c, a, b)                                                     \
    asm volatile("mma.sync.aligned.m16n8k8.row.col.f32.tf32.tf32.f32 "        \
        "{%0,%1,%2,%3}, {%4,%5,%6,%7}, {%8,%9}, {%0,%1,%2,%3};"               \
        : "+f"((c)[0]), "+f"((c)[1]), "+f"((c)[2]), "+f"((c)[3])              \
        : "r"((a)[0]), "r"((a)[1]), "r"((a)[2]), "r"((a)[3]),                 \
          "r"((b)[0]), "r"((b)[1]))

// ---------------------------------------------------------------------------
__global__ void prep_w_kernel(const float* __restrict__ qw,
                              const float* __restrict__ qb,
                              const float* __restrict__ pw) {
    int t = blockIdx.x * blockDim.x + threadIdx.x;
    if (t < 512 * 1536) {
        int k  = t / 1536;
        int jn = t - k * 1536;           // jn = s*512 + h*32 + d
        int s  = jn >> 9;
        int r  = jn & 511;
        int h  = r >> 5;
        int d  = r & 31;
        int jo = d * 48 + h * 3 + s;
        float v = qw[k * 1536 + jo];
        if (s == 0) v *= SCALE_Q;
        g_w[t] = rna_tf32(v);
    }
    if (t < 512 * 512) g_pw[t] = rna_tf32(pw[t]);
    if (t < 1536) {
        int s = t >> 9;
        int r = t & 511;
        int h = r >> 5;
        int d = r & 31;
        int jo = d * 48 + h * 3 + s;
        float v = qb[jo];
        if (s == 0) v *= SCALE_Q;
        g_bvec[t] = v;
    }
}

// Transpose + tf32-round x: (b, c, n) -> g_xr[(b*49+n)*512 + c]
// block handles (b, quarter of c=128). smem [128][51] pad -> conflict-free.
__global__ __launch_bounds__(256) void prep_xt_kernel(const float* __restrict__ x) {
    __shared__ float s[128][51];
    const int b  = blockIdx.y;
    const int ch = blockIdx.x;            // 0..3
    const int tid = threadIdx.x;
    const float* src = x + (long)b * 25088 + ch * 128 * 49;
    for (int idx = tid; idx < 6272; idx += 256) {
        int c = idx / 49;
        int n = idx - c * 49;
        s[c][n] = rna_tf32(src[idx]);
    }
    __syncthreads();
    float* dst = g_xr + (long)b * 25088 + ch * 128;
    for (int idx = tid; idx < 6272; idx += 256) {
        int n = idx >> 7;
        int c = idx & 127;
        dst[(long)n * 512 + c] = s[c][n];
    }
}

__global__ void prep_bm_kernel(const float* __restrict__ mask,
                               const float* __restrict__ table) {
    int t = blockIdx.x * blockDim.x + threadIdx.x;
    if (t >= 64 * 16 * 2401) return;
    int w = t / (16 * 2401);
    int r = t - w * (16 * 2401);
    int h = r / 2401;
    int e = r - h * 2401;
    int n = e / 49;
    int m = e - n * 49;
    int di = n / 7 - m / 7 + 6;
    int dj = (n % 7) - (m % 7) + 6;
    int idx = di * 6 + dj;
    g_bm[t] = table[idx * 16 + h] + mask[w * 2401 + e];
}

// ---------------------------------------------------------------------------
// Shared GEMM skeleton: block 128x128, K=512, 16-k chunks, 3-stage cp.async,
// one __syncthreads per chunk. smem per stage: A 128x20 fl + B 16x136 fl.
// stage stride = 4736 floats = 18944 bytes. Total dynamic smem 56832 B.

#define GEMM_COMPUTE(Aptr, Bptr)                                              \
    {                                                                         \
        const float* A = (Aptr);                                              \
        const float* B = (Bptr);                                              \
        _Pragma("unroll")                                                     \
        for (int ks = 0; ks < 2; ks++) {                                      \
            uint32_t af[4][4], bf[4][2];                                      \
            _Pragma("unroll")                                                 \
            for (int tm = 0; tm < 4; tm++) {                                  \
                const float* p = A + aro + tm * 320 + ks * 8;                 \
                af[tm][0] = __float_as_uint(p[0]);                            \
                af[tm][1] = __float_as_uint(p[160]);                          \
                af[tm][2] = __float_as_uint(p[4]);                            \
                af[tm][3] = __float_as_uint(p[164]);                          \
            }                                                                 \
            _Pragma("unroll")                                                 \
            for (int tn = 0; tn < 4; tn++) {                                  \
                const float* p = B + ks * 1088 + bro + tn * 8;                \
                bf[tn][0] = __float_as_uint(p[0]);                            \
                bf[tn][1] = __float_as_uint(p[544]);                          \
            }                                                                 \
            _Pragma("unroll")                                                 \
            for (int tm = 0; tm < 4; tm++)                                    \
                _Pragma("unroll")                                             \
                for (int tn = 0; tn < 4; tn++)                                \
                    MMA_TF32(acc[tm][tn], af[tm], bf[tn]);                    \
        }                                                                     \
    }

// QKV GEMM: C[M,1536] = g_xr[M,512] @ g_w[512,1536] + g_bvec
__global__ __launch_bounds__(256) void gemm_qkv_tc() {
    extern __shared__ __align__(16) float sm[];
    const int tid  = threadIdx.x;
    const int lane = tid & 31, warp = tid >> 5;
    const int wm = warp >> 2, wn = warp & 3;
    const int m0 = blockIdx.y << 7;
    const int n0 = blockIdx.x << 7;

    uint32_t smem_u = (uint32_t)__cvta_generic_to_shared(sm);

    const int pm  = tid >> 2;                 // 0..63
    const int pk4 = (tid & 3) * 4;
    const float* a_src0 = g_xr + (long)(m0 + pm) * 512 + pk4;
    const uint32_t a_dst0 = smem_u + (pm * 20 + pk4) * 4;

    const int bk  = tid >> 5;                 // 0..7
    const int bc4 = (tid & 31) * 4;
    const float* b_src0 = g_w + bk * 1536 + n0 + bc4;
    const uint32_t b_dst0 = smem_u + 10240 + (bk * 136 + bc4) * 4;

#define QKV_LOAD(kc, s)                                                        \
    {                                                                          \
        const float* ap = a_src0 + (kc) * 16;                                  \
        uint32_t ad = a_dst0 + (s) * 18944;                                    \
        cp_async16(ad, ap); cp_async16(ad + 5120, ap + 32768);                 \
        const float* bp = b_src0 + (kc) * 24576;                               \
        uint32_t bd = b_dst0 + (s) * 18944;                                    \
        cp_async16(bd, bp); cp_async16(bd + 4352, bp + 12288);                 \
    }

    float acc[4][4][4] = {};
    const int aro = (wm * 64 + (lane >> 2)) * 20 + (lane & 3);
    const int bro = (lane & 3) * 136 + wn * 32 + (lane >> 2);

    QKV_LOAD(0, 0); CP_COMMIT();
    QKV_LOAD(1, 1); CP_COMMIT();
    int sl = 2, sc = 0;
    for (int kc = 0; kc < 32; kc++) {
        CP_WAIT1();
        __syncthreads();
        if (kc < 30) QKV_LOAD(kc + 2, sl);
        CP_COMMIT();
        GEMM_COMPUTE(sm + sc * 4736, sm + sc * 4736 + 2560);
        sl = (sl == 2) ? 0 : sl + 1;
        sc = (sc == 2) ? 0 : sc + 1;
    }

#pragma unroll
    for (int tm = 0; tm < 4; tm++) {
        int r = m0 + wm * 64 + tm * 16 + (lane >> 2);
#pragma unroll
        for (int tn = 0; tn < 4; tn++) {
            int cidx = n0 + wn * 32 + tn * 8 + (lane & 3) * 2;
            float b0 = g_bvec[cidx], b1 = g_bvec[cidx + 1];
            float2 v0 = {acc[tm][tn][0] + b0, acc[tm][tn][1] + b1};
            float2 v1 = {acc[tm][tn][2] + b0, acc[tm][tn][3] + b1};
            *(float2*)(g_qkv + (long)r * 1536 + cidx)       = v0;
            *(float2*)(g_qkv + (long)(r + 8) * 1536 + cidx) = v1;
        }
    }
}

// ---------------------------------------------------------------------------
// Attention, register-tiled. 192 threads per (b,h).
// QK: 169 threads x (4x4 S-tile), float4 d-loads. PV: 104 threads x (4i x 4d).
__global__ __launch_bounds__(192) void attn_kernel() {
    const int h = blockIdx.x;
    const int b = blockIdx.y;
    const int w = b & 63;
    const int tid = threadIdx.x;

    __shared__ float sq[52][36];
    __shared__ float sk[52][36];
    __shared__ float sv[49][36];
    __shared__ float sS[52][52];
    __shared__ float sinv[49];

    const float* base = g_qkv + (long)b * 75264 + h * 32;
    for (int t = tid; t < 416; t += 192) {
        int n = t >> 3, d = (t & 7) << 2;
        if (n < 49) {
            const float* rp = base + n * 1536 + d;
            *(float4*)&sq[n][d] = *(const float4*)(rp);
            *(float4*)&sk[n][d] = *(const float4*)(rp + 512);
            *(float4*)&sv[n][d] = *(const float4*)(rp + 1024);
        } else {
            float4 z = {0.f, 0.f, 0.f, 0.f};
            *(float4*)&sq[n][d] = z;
            *(float4*)&sk[n][d] = z;
        }
    }
    const float* bm = g_bm + (w * 16 + h) * 2401;
    for (int e = tid; e < 2401; e += 192) {
        int i = e / 49;
        int j = e - i * 49;
        sS[i][j] = bm[e];
    }
    __syncthreads();

    if (tid < 169) {
        int ti = tid / 13, tj = tid - ti * 13;
        int i0 = ti * 4, j0 = tj * 4;
        float acc[4][4] = {};
#pragma unroll
        for (int d4 = 0; d4 < 32; d4 += 4) {
            float4 qa[4], ka[4];
#pragma unroll
            for (int r = 0; r < 4; r++) qa[r] = *(float4*)&sq[i0 + r][d4];
#pragma unroll
            for (int r = 0; r < 4; r++) ka[r] = *(float4*)&sk[j0 + r][d4];
#pragma unroll
            for (int r = 0; r < 4; r++)
#pragma unroll
                for (int cc = 0; cc < 4; cc++) {
                    acc[r][cc] = fmaf(qa[r].x, ka[cc].x, acc[r][cc]);
                    acc[r][cc] = fmaf(qa[r].y, ka[cc].y, acc[r][cc]);
                    acc[r][cc] = fmaf(qa[r].z, ka[cc].z, acc[r][cc]);
                    acc[r][cc] = fmaf(qa[r].w, ka[cc].w, acc[r][cc]);
                }
        }
#pragma unroll
        for (int r = 0; r < 4; r++)
            if (i0 + r < 49)
#pragma unroll
                for (int cc = 0; cc < 4; cc++)
                    if (j0 + cc < 49)
                        sS[i0 + r][j0 + cc] += acc[r][cc];
    }
    __syncthreads();

    if (tid < 49) {
        float mx = -1e30f;
#pragma unroll
        for (int j = 0; j < 49; j++) mx = fmaxf(mx, sS[tid][j]);
        float s = 0.f;
#pragma unroll
        for (int j = 0; j < 49; j++) {
            float p = __expf(sS[tid][j] - mx);
            sS[tid][j] = p;
            s += p;
        }
        sinv[tid] = 1.0f / s;
    }
    __syncthreads();

    if (tid < 104) {
        int ti = tid >> 3, td = tid & 7;
        int i0 = ti * 4, d0 = td * 4;
        float4 acc[4] = {};
        for (int j = 0; j < 49; j++) {
            float4 v4 = *(float4*)&sv[j][d0];
#pragma unroll
            for (int r = 0; r < 4; r++) {
                float p = sS[i0 + r][j];
                acc[r].x = fmaf(p, v4.x, acc[r].x);
                acc[r].y = fmaf(p, v4.y, acc[r].y);
                acc[r].z = fmaf(p, v4.z, acc[r].z);
                acc[r].w = fmaf(p, v4.w, acc[r].w);
            }
        }
        float* ob = g_ao + (long)b * 25088 + h * 32 + d0;
#pragma unroll
        for (int r = 0; r < 4; r++) {
            int i = i0 + r;
            if (i < 49) {
                float si = sinv[i];
                float4 o;
                o.x = rna_tf32(acc[r].x * si);
                o.y = rna_tf32(acc[r].y * si);
                o.z = rna_tf32(acc[r].z * si);
                o.w = rna_tf32(acc[r].w * si);
                *(float4*)(ob + (long)i * 512) = o;
            }
        }
    }
}

// ---------------------------------------------------------------------------
// Proj GEMM: Y = g_ao @ g_pw + proj_b, stored transposed (b,c,n).
__global__ __launch_bounds__(256) void gemm_proj_tc(const float* __restrict__ pb,
                                                    float* __restrict__ out) {
    extern __shared__ __align__(16) float sm[];
    const int tid  = threadIdx.x;
    const int lane = tid & 31, warp = tid >> 5;
    const int wm = warp >> 2, wn = warp & 3;
    const int m0 = blockIdx.y << 7;
    const int n0 = blockIdx.x << 7;

    uint32_t smem_u = (uint32_t)__cvta_generic_to_shared(sm);

    const int pm  = tid >> 2;
    const int pk4 = (tid & 3) * 4;
    const float* a_src0 = g_ao + (long)(m0 + pm) * 512 + pk4;
    const uint32_t a_dst0 = smem_u + (pm * 20 + pk4) * 4;

    const int bk  = tid >> 5;
    const int bc4 = (tid & 31) * 4;
    const float* b_src0 = g_pw + bk * 512 + n0 + bc4;
    const uint32_t b_dst0 = smem_u + 10240 + (bk * 136 + bc4) * 4;

#define PROJ_LOAD(kc, s)                                                       \
    {                                                                          \
        const float* ap = a_src0 + (kc) * 16;                                  \
        uint32_t ad = a_dst0 + (s) * 18944;                                    \
        cp_async16(ad, ap); cp_async16(ad + 5120, ap + 32768);                 \
        const float* bp = b_src0 + (kc) * 8192;                                \
        uint32_t bd = b_dst0 + (s) * 18944;                                    \
        cp_async16(bd, bp); cp_async16(bd + 4352, bp + 4096);                  \
    }

    float acc[4][4][4] = {};
    const int aro = (wm * 64 + (lane >> 2)) * 20 + (lane & 3);
    const int bro = (lane & 3) * 136 + wn * 32 + (lane >> 2);

    PROJ_LOAD(0, 0); CP_COMMIT();
    PROJ_LOAD(1, 1); CP_COMMIT();
    int sl = 2, sc = 0;
    for (int kc = 0; kc < 32; kc++) {
        CP_WAIT1();
        __syncthreads();
        if (kc < 30) PROJ_LOAD(kc + 2, sl);
        CP_COMMIT();
        GEMM_COMPUTE(sm + sc * 4736, sm + sc * 4736 + 2560);
        sl = (sl == 2) ? 0 : sl + 1;
        sc = (sc == 2) ? 0 : sc + 1;
    }

    // Transposed epilogue via smem staging, two 64-column halves.
    float* stg = sm;                       // [128][66]
    const int r_l  = tid & 127;
    int rowg = m0 + r_l;
    int ob_b = rowg / 49;
    int ob_n = rowg - ob_b * 49;
    float* obase = out + (long)ob_b * 25088 + ob_n;
    const int ccb = tid >> 7;              // 0 or 1

    for (int half = 0; half < 2; half++) {
        __syncthreads();
        if ((wn >> 1) == half) {
#pragma unroll
            for (int tm = 0; tm < 4; tm++) {
                int rl = wm * 64 + tm * 16 + (lane >> 2);
#pragma unroll
                for (int tn = 0; tn < 4; tn++) {
                    int cl = (wn & 1) * 32 + tn * 8 + (lane & 3) * 2;
                    int cg = n0 + half * 64 + cl;
                    float b0 = pb[cg], b1 = pb[cg + 1];
                    stg[rl * 66 + cl]           = acc[tm][tn][0] + b0;
                    stg[rl * 66 + cl + 1]       = acc[tm][tn][1] + b1;
                    stg[(rl + 8) * 66 + cl]     = acc[tm][tn][2] + b0;
                    stg[(rl + 8) * 66 + cl + 1] = acc[tm][tn][3] + b1;
                }
            }
        }
        __syncthreads();
#pragma unroll
        for (int i = 0; i < 32; i++) {
            int cc = ccb + 2 * i;
            int ch = n0 + half * 64 + cc;
            obase[(long)ch * 49] = stg[r_l * 66 + cc];
        }
    }
}

// ---------------------------------------------------------------------------
extern "C" void kernel_launch(void* const* d_in, const int* in_sizes, int n_in,
                              void* d_out, int out_size) {
    const float *x = nullptr, *mask = nullptr, *table = nullptr;
    const float *qw = nullptr, *qb = nullptr, *pw = nullptr, *pb = nullptr;
    for (int i = 0; i < n_in; i++) {
        const float* p = (const float*)d_in[i];
        switch (in_sizes[i]) {
            case 51380224: x = p; break;
            case 153664:   mask = p; break;
            case 2704:     table = p; break;
            case 786432:   qw = p; break;
            case 1536:     qb = p; break;
            case 262144:   pw = p; break;
            case 512:      pb = p; break;
        }
    }
    float* out = (float*)d_out;

    const int smem_bytes = 56832;   // 3 stages * 4736 floats
    cudaFuncSetAttribute(gemm_qkv_tc,  cudaFuncAttributeMaxDynamicSharedMemorySize, smem_bytes);
    cudaFuncSetAttribute(gemm_proj_tc, cudaFuncAttributeMaxDynamicSharedMemorySize, smem_bytes);

    prep_w_kernel<<<(512 * 1536 + 255) / 256, 256>>>(qw, qb, pw);
    prep_bm_kernel<<<(64 * 16 * 2401 + 255) / 256, 256>>>(mask, table);
    prep_xt_kernel<<<dim3(4, 2048), 256>>>(x);
    gemm_qkv_tc<<<dim3(12, 784), 256, smem_bytes>>>();
    attn_kernel<<<dim3(16, 2048), 192>>>();
    gemm_proj_tc<<<dim3(4, 784), 256, smem_bytes>>>(pb, out);
}

// round 5
// speedup vs baseline: 3.5455x; 1.4662x over previous
#include <cuda_runtime.h>
#include <cuda_fp16.h>
#include <cstdint>

// ---------------------------------------------------------------------------
// WindowAttention: x(2048,512,7,7) -> out(2048,512,7,7)
// bs=2048, c=512, ws=7, N=49, H=16, hd=32, n_windows=64, M=bs*N=100352
// Round 5: fp16 m16n8k16 HMMA GEMMs (fp32 accum), k-chunk 64, 3-stage
//          cp.async. tcgen05 unavailable (-arch=sm_100 toolchain target).
// ---------------------------------------------------------------------------

#define SCALE_Q 0.17677669529663687f   // 32^-0.5

__device__ __half g_wth[1536 * 512];       //   1.5 MB  qkv weight [N][K], fp16
__device__ __half g_pwt[512 * 512];        //   0.5 MB  proj weight [N][K], fp16
__device__ float  g_bvec[1536];            //           permuted qkv bias (exact)
__device__ float  g_bm[64 * 16 * 2401];    //   9.8 MB  fused bias+mask
__device__ __half g_xh[51380224];          // 102.8 MB  fp16 transposed x: [M][512]
__device__ float  g_qkv[154140672];        // 616.6 MB  M x 1536 fp32
__device__ __half g_aoh[51380224];         // 102.8 MB  M x 512 fp16

__device__ __forceinline__ void cp_async16(uint32_t dst, const void* src) {
    asm volatile("cp.async.cg.shared.global [%0], [%1], 16;" :: "r"(dst), "l"(src));
}
#define CP_COMMIT() asm volatile("cp.async.commit_group;")
#define CP_WAIT1()  asm volatile("cp.async.wait_group 1;")

#define MMA_F16(c, a, b)                                                      \
    asm volatile("mma.sync.aligned.m16n8k16.row.col.f32.f16.f16.f32 "         \
        "{%0,%1,%2,%3}, {%4,%5,%6,%7}, {%8,%9}, {%0,%1,%2,%3};"               \
        : "+f"((c)[0]), "+f"((c)[1]), "+f"((c)[2]), "+f"((c)[3])              \
        : "r"((a)[0]), "r"((a)[1]), "r"((a)[2]), "r"((a)[3]),                 \
          "r"((b)[0]), "r"((b)[1]))

// ---------------------------------------------------------------------------
__global__ void prep_w_kernel(const float* __restrict__ qw,
                              const float* __restrict__ qb,
                              const float* __restrict__ pw) {
    int t = blockIdx.x * blockDim.x + threadIdx.x;
    if (t < 512 * 1536) {
        int k  = t / 1536;
        int jn = t - k * 1536;           // jn = s*512 + h*32 + d
        int s  = jn >> 9;
        int r  = jn & 511;
        int h  = r >> 5;
        int d  = r & 31;
        int jo = d * 48 + h * 3 + s;     // source col in (hd, heads, 3) packing
        float v = qw[k * 1536 + jo];
        if (s == 0) v *= SCALE_Q;
        g_wth[jn * 512 + k] = __float2half_rn(v);   // [N][K] n-major
    }
    if (t < 512 * 512) {
        int k = t >> 9;
        int n = t & 511;
        g_pwt[n * 512 + k] = __float2half_rn(pw[t]);
    }
    if (t < 1536) {
        int s = t >> 9;
        int r = t & 511;
        int h = r >> 5;
        int d = r & 31;
        int jo = d * 48 + h * 3 + s;
        float v = qb[jo];
        if (s == 0) v *= SCALE_Q;
        g_bvec[t] = v;
    }
}

// Transpose + fp16-round x: (b, c, n) -> g_xh[(b*49+n)*512 + c]
__global__ __launch_bounds__(256) void prep_xt_kernel(const float* __restrict__ x) {
    __shared__ float s[128][51];
    const int b  = blockIdx.y;
    const int ch = blockIdx.x;            // 0..3
    const int tid = threadIdx.x;
    const float* src = x + (long)b * 25088 + ch * 128 * 49;
    for (int idx = tid; idx < 6272; idx += 256) {
        int c = idx / 49;
        int n = idx - c * 49;
        s[c][n] = src[idx];
    }
    __syncthreads();
    __half* dst = g_xh + (long)b * 25088 + ch * 128;
    for (int idx = tid; idx < 6272; idx += 256) {
        int n = idx >> 7;
        int c = idx & 127;
        dst[(long)n * 512 + c] = __float2half_rn(s[c][n]);
    }
}

__global__ void prep_bm_kernel(const float* __restrict__ mask,
                               const float* __restrict__ table) {
    int t = blockIdx.x * blockDim.x + threadIdx.x;
    if (t >= 64 * 16 * 2401) return;
    int w = t / (16 * 2401);
    int r = t - w * (16 * 2401);
    int h = r / 2401;
    int e = r - h * 2401;
    int n = e / 49;
    int m = e - n * 49;
    int di = n / 7 - m / 7 + 6;
    int dj = (n % 7) - (m % 7) + 6;
    int idx = di * 6 + dj;
    g_bm[t] = table[idx * 16 + h] + mask[w * 2401 + e];
}

// ---------------------------------------------------------------------------
// fp16 GEMM core: block 128x128, K=512 in 8 chunks of 64, 3-stage cp.async.
// smem stage: A[128][72]h (18432 B) + B[128][72]h -> 36864 B/stage, 110592 B.
// 8 warps, warp tile 64x32, 4 k-steps of m16n8k16 per chunk.

#define HGEMM_COMPUTE(sbase)                                                  \
    {                                                                         \
        const __half* A = (sbase);                                            \
        const __half* B = (sbase) + 9216;                                     \
        _Pragma("unroll")                                                     \
        for (int ks = 0; ks < 4; ks++) {                                      \
            uint32_t af[4][4], bf[4][2];                                      \
            _Pragma("unroll")                                                 \
            for (int tm = 0; tm < 4; tm++) {                                  \
                const __half* p = A + aro + tm * 1152 + ks * 16;              \
                af[tm][0] = *(const uint32_t*)(p);                            \
                af[tm][1] = *(const uint32_t*)(p + 576);                      \
                af[tm][2] = *(const uint32_t*)(p + 8);                        \
                af[tm][3] = *(const uint32_t*)(p + 584);                      \
            }                                                                 \
            _Pragma("unroll")                                                 \
            for (int tn = 0; tn < 4; tn++) {                                  \
                const __half* p = B + bro + tn * 576 + ks * 16;               \
                bf[tn][0] = *(const uint32_t*)(p);                            \
                bf[tn][1] = *(const uint32_t*)(p + 8);                        \
            }                                                                 \
            _Pragma("unroll")                                                 \
            for (int tm = 0; tm < 4; tm++)                                    \
                _Pragma("unroll")                                             \
                for (int tn = 0; tn < 4; tn++)                                \
                    MMA_F16(acc[tm][tn], af[tm], bf[tn]);                     \
        }                                                                     \
    }

#define HGEMM_PIPE(LOADM)                                                     \
    LOADM(0, 0); CP_COMMIT();                                                 \
    LOADM(1, 1); CP_COMMIT();                                                 \
    {                                                                         \
        int sl = 2, sc = 0;                                                   \
        for (int kc = 0; kc < 8; kc++) {                                      \
            CP_WAIT1();                                                       \
            __syncthreads();                                                  \
            if (kc < 6) LOADM(kc + 2, sl);                                    \
            CP_COMMIT();                                                      \
            HGEMM_COMPUTE(smh + sc * 18432);                                  \
            sl = (sl == 2) ? 0 : sl + 1;                                      \
            sc = (sc == 2) ? 0 : sc + 1;                                      \
        }                                                                     \
    }

// QKV GEMM: C[M,1536] = g_xh[M,512] @ g_wth^T + g_bvec  -> g_qkv fp32
__global__ __launch_bounds__(256) void gemm_qkv_h() {
    extern __shared__ __align__(16) char smem[];
    __half* smh = (__half*)smem;
    const int tid  = threadIdx.x;
    const int lane = tid & 31, warp = tid >> 5;
    const int wm = warp >> 2, wn = warp & 3;
    const int m0 = blockIdx.y << 7;
    const int n0 = blockIdx.x << 7;
    const uint32_t smem_u = (uint32_t)__cvta_generic_to_shared(smem);

    const int r0  = tid >> 3;             // 0..31
    const int c16 = tid & 7;              // 16B segment within 128B row
    const __half* a_src = g_xh  + (long)(m0 + r0) * 512 + c16 * 8;
    const __half* b_src = g_wth + (long)(n0 + r0) * 512 + c16 * 8;
    const uint32_t a_dst = smem_u + r0 * 144 + c16 * 16;
    const uint32_t b_dst = a_dst + 18432;

#define QKV_HLOAD(kc, s)                                                       \
    {                                                                          \
        const __half* ap = a_src + (kc) * 64;                                  \
        uint32_t ad = a_dst + (s) * 36864;                                     \
        _Pragma("unroll")                                                      \
        for (int i = 0; i < 4; i++)                                            \
            cp_async16(ad + i * 4608, ap + i * 16384);                         \
        const __half* bp = b_src + (kc) * 64;                                  \
        uint32_t bd = b_dst + (s) * 36864;                                     \
        _Pragma("unroll")                                                      \
        for (int i = 0; i < 4; i++)                                            \
            cp_async16(bd + i * 4608, bp + i * 16384);                         \
    }

    float acc[4][4][4] = {};
    const int aro = (wm * 64 + (lane >> 2)) * 72 + (lane & 3) * 2;
    const int bro = (wn * 32 + (lane >> 2)) * 72 + (lane & 3) * 2;

    HGEMM_PIPE(QKV_HLOAD)

#pragma unroll
    for (int tm = 0; tm < 4; tm++) {
        int r = m0 + wm * 64 + tm * 16 + (lane >> 2);
#pragma unroll
        for (int tn = 0; tn < 4; tn++) {
            int cidx = n0 + wn * 32 + tn * 8 + (lane & 3) * 2;
            float b0 = g_bvec[cidx], b1 = g_bvec[cidx + 1];
            float2 v0 = {acc[tm][tn][0] + b0, acc[tm][tn][1] + b1};
            float2 v1 = {acc[tm][tn][2] + b0, acc[tm][tn][3] + b1};
            *(float2*)(g_qkv + (long)r * 1536 + cidx)       = v0;
            *(float2*)(g_qkv + (long)(r + 8) * 1536 + cidx) = v1;
        }
    }
}

// ---------------------------------------------------------------------------
// Attention, register-tiled fp32 (round-3 structure; writes fp16 g_aoh).
__global__ __launch_bounds__(192) void attn_kernel() {
    const int h = blockIdx.x;
    const int b = blockIdx.y;
    const int w = b & 63;
    const int tid = threadIdx.x;

    __shared__ float sq[52][36];
    __shared__ float sk[52][36];
    __shared__ float sv[49][36];
    __shared__ float sS[52][52];
    __shared__ float sinv[49];

    const float* base = g_qkv + (long)b * 75264 + h * 32;
    for (int t = tid; t < 416; t += 192) {
        int n = t >> 3, d = (t & 7) << 2;
        if (n < 49) {
            const float* rp = base + n * 1536 + d;
            *(float4*)&sq[n][d] = *(const float4*)(rp);
            *(float4*)&sk[n][d] = *(const float4*)(rp + 512);
            *(float4*)&sv[n][d] = *(const float4*)(rp + 1024);
        } else {
            float4 z = {0.f, 0.f, 0.f, 0.f};
            *(float4*)&sq[n][d] = z;
            *(float4*)&sk[n][d] = z;
        }
    }
    const float* bm = g_bm + (w * 16 + h) * 2401;
    for (int e = tid; e < 2401; e += 192) {
        int i = e / 49;
        int j = e - i * 49;
        sS[i][j] = bm[e];
    }
    __syncthreads();

    if (tid < 169) {
        int ti = tid / 13, tj = tid - ti * 13;
        int i0 = ti * 4, j0 = tj * 4;
        float acc[4][4] = {};
#pragma unroll
        for (int d4 = 0; d4 < 32; d4 += 4) {
            float4 qa[4], ka[4];
#pragma unroll
            for (int r = 0; r < 4; r++) qa[r] = *(float4*)&sq[i0 + r][d4];
#pragma unroll
            for (int r = 0; r < 4; r++) ka[r] = *(float4*)&sk[j0 + r][d4];
#pragma unroll
            for (int r = 0; r < 4; r++)
#pragma unroll
                for (int cc = 0; cc < 4; cc++) {
                    acc[r][cc] = fmaf(qa[r].x, ka[cc].x, acc[r][cc]);
                    acc[r][cc] = fmaf(qa[r].y, ka[cc].y, acc[r][cc]);
                    acc[r][cc] = fmaf(qa[r].z, ka[cc].z, acc[r][cc]);
                    acc[r][cc] = fmaf(qa[r].w, ka[cc].w, acc[r][cc]);
                }
        }
#pragma unroll
        for (int r = 0; r < 4; r++)
            if (i0 + r < 49)
#pragma unroll
                for (int cc = 0; cc < 4; cc++)
                    if (j0 + cc < 49)
                        sS[i0 + r][j0 + cc] += acc[r][cc];
    }
    __syncthreads();

    if (tid < 49) {
        float mx = -1e30f;
#pragma unroll
        for (int j = 0; j < 49; j++) mx = fmaxf(mx, sS[tid][j]);
        float s = 0.f;
#pragma unroll
        for (int j = 0; j < 49; j++) {
            float p = __expf(sS[tid][j] - mx);
            sS[tid][j] = p;
            s += p;
        }
        sinv[tid] = 1.0f / s;
    }
    __syncthreads();

    if (tid < 104) {
        int ti = tid >> 3, td = tid & 7;
        int i0 = ti * 4, d0 = td * 4;
        float4 acc[4] = {};
        for (int j = 0; j < 49; j++) {
            float4 v4 = *(float4*)&sv[j][d0];
#pragma unroll
            for (int r = 0; r < 4; r++) {
                float p = sS[i0 + r][j];
                acc[r].x = fmaf(p, v4.x, acc[r].x);
                acc[r].y = fmaf(p, v4.y, acc[r].y);
                acc[r].z = fmaf(p, v4.z, acc[r].z);
                acc[r].w = fmaf(p, v4.w, acc[r].w);
            }
        }
        __half* ob = g_aoh + (long)b * 25088 + h * 32 + d0;
#pragma unroll
        for (int r = 0; r < 4; r++) {
            int i = i0 + r;
            if (i < 49) {
                float si = sinv[i];
                __half2 h01 = __floats2half2_rn(acc[r].x * si, acc[r].y * si);
                __half2 h23 = __floats2half2_rn(acc[r].z * si, acc[r].w * si);
                __half2* op = (__half2*)(ob + (long)i * 512);
                op[0] = h01;
                op[1] = h23;
            }
        }
    }
}

// ---------------------------------------------------------------------------
// Proj GEMM (fp16 HMMA): Y = g_aoh @ g_pwt^T + proj_b, stored transposed.
__global__ __launch_bounds__(256) void gemm_proj_h(const float* __restrict__ pb,
                                                   float* __restrict__ out) {
    extern __shared__ __align__(16) char smem[];
    __half* smh = (__half*)smem;
    float*  smf = (float*)smem;
    const int tid  = threadIdx.x;
    const int lane = tid & 31, warp = tid >> 5;
    const int wm = warp >> 2, wn = warp & 3;
    const int m0 = blockIdx.y << 7;
    const int n0 = blockIdx.x << 7;
    const uint32_t smem_u = (uint32_t)__cvta_generic_to_shared(smem);

    const int r0  = tid >> 3;
    const int c16 = tid & 7;
    const __half* a_src = g_aoh + (long)(m0 + r0) * 512 + c16 * 8;
    const __half* b_src = g_pwt + (long)(n0 + r0) * 512 + c16 * 8;
    const uint32_t a_dst = smem_u + r0 * 144 + c16 * 16;
    const uint32_t b_dst = a_dst + 18432;

#define PROJ_HLOAD(kc, s)                                                      \
    {                                                                          \
        const __half* ap = a_src + (kc) * 64;                                  \
        uint32_t ad = a_dst + (s) * 36864;                                     \
        _Pragma("unroll")                                                      \
        for (int i = 0; i < 4; i++)                                            \
            cp_async16(ad + i * 4608, ap + i * 16384);                         \
        const __half* bp = b_src + (kc) * 64;                                  \
        uint32_t bd = b_dst + (s) * 36864;                                     \
        _Pragma("unroll")                                                      \
        for (int i = 0; i < 4; i++)                                            \
            cp_async16(bd + i * 4608, bp + i * 16384);                         \
    }

    float acc[4][4][4] = {};
    const int aro = (wm * 64 + (lane >> 2)) * 72 + (lane & 3) * 2;
    const int bro = (wn * 32 + (lane >> 2)) * 72 + (lane & 3) * 2;

    HGEMM_PIPE(PROJ_HLOAD)

    // Transposed epilogue via smem staging, two 64-column halves.
    float* stg = smf;                      // [128][66]
    const int r_l  = tid & 127;
    int rowg = m0 + r_l;
    int ob_b = rowg / 49;
    int ob_n = rowg - ob_b * 49;
    float* obase = out + (long)ob_b * 25088 + ob_n;
    const int ccb = tid >> 7;

    for (int half = 0; half < 2; half++) {
        __syncthreads();
        if ((wn >> 1) == half) {
#pragma unroll
            for (int tm = 0; tm < 4; tm++) {
                int rl = wm * 64 + tm * 16 + (lane >> 2);
#pragma unroll
                for (int tn = 0; tn < 4; tn++) {
                    int cl = (wn & 1) * 32 + tn * 8 + (lane & 3) * 2;
                    int cg = n0 + half * 64 + cl;
                    float b0 = pb[cg], b1 = pb[cg + 1];
                    stg[rl * 66 + cl]           = acc[tm][tn][0] + b0;
                    stg[rl * 66 + cl + 1]       = acc[tm][tn][1] + b1;
                    stg[(rl + 8) * 66 + cl]     = acc[tm][tn][2] + b0;
                    stg[(rl + 8) * 66 + cl + 1] = acc[tm][tn][3] + b1;
                }
            }
        }
        __syncthreads();
#pragma unroll
        for (int i = 0; i < 32; i++) {
            int cc = ccb + 2 * i;
            int ch = n0 + half * 64 + cc;
            obase[(long)ch * 49] = stg[r_l * 66 + cc];
        }
    }
}

// ---------------------------------------------------------------------------
extern "C" void kernel_launch(void* const* d_in, const int* in_sizes, int n_in,
                              void* d_out, int out_size) {
    const float *x = nullptr, *mask = nullptr, *table = nullptr;
    const float *qw = nullptr, *qb = nullptr, *pw = nullptr, *pb = nullptr;
    for (int i = 0; i < n_in; i++) {
        const float* p = (const float*)d_in[i];
        switch (in_sizes[i]) {
            case 51380224: x = p; break;
            case 153664:   mask = p; break;
            case 2704:     table = p; break;
            case 786432:   qw = p; break;
            case 1536:     qb = p; break;
            case 262144:   pw = p; break;
            case 512:      pb = p; break;
        }
    }
    float* out = (float*)d_out;

    const int gemm_smem = 110592;   // 3 stages * 36864 B
    cudaFuncSetAttribute(gemm_qkv_h,  cudaFuncAttributeMaxDynamicSharedMemorySize, gemm_smem);
    cudaFuncSetAttribute(gemm_proj_h, cudaFuncAttributeMaxDynamicSharedMemorySize, gemm_smem);

    prep_w_kernel<<<(512 * 1536 + 255) / 256, 256>>>(qw, qb, pw);
    prep_bm_kernel<<<(64 * 16 * 2401 + 255) / 256, 256>>>(mask, table);
    prep_xt_kernel<<<dim3(4, 2048), 256>>>(x);
    gemm_qkv_h<<<dim3(12, 784), 256, gemm_smem>>>();
    attn_kernel<<<dim3(16, 2048), 192>>>();
    gemm_proj_h<<<dim3(4, 784), 256, gemm_smem>>>(pb, out);
}

// round 6
// speedup vs baseline: 4.1229x; 1.1628x over previous
#include <cuda_runtime.h>
#include <cuda_fp16.h>
#include <cstdint>

// ---------------------------------------------------------------------------
// WindowAttention: x(2048,512,7,7) -> out(2048,512,7,7)
// bs=2048, c=512, ws=7, N=49, H=16, hd=32, n_windows=64, M=bs*N=100352
// Round 6: ldmatrix fragment loads in HMMA GEMMs; q/k/v packed fp16
//          [b][h][49][32]; fp16-smem attention.
// ---------------------------------------------------------------------------

#define SCALE_Q 0.17677669529663687f   // 32^-0.5

__device__ __half g_wth[1536 * 512];       //   1.5 MB  qkv weight [N][K], fp16
__device__ __half g_pwt[512 * 512];        //   0.5 MB  proj weight [N][K], fp16
__device__ float  g_bvec[1536];            //           permuted qkv bias (exact)
__device__ float  g_bm[64 * 16 * 2401];    //   9.8 MB  fused bias+mask
__device__ __half g_xh[51380224];          // 102.8 MB  fp16 transposed x: [M][512]
__device__ __half g_qh[51380224];          // 102.8 MB  q fp16 [b][h][49][32]
__device__ __half g_kh[51380224];          // 102.8 MB  k fp16 [b][h][49][32]
__device__ __half g_vh[51380224];          // 102.8 MB  v fp16 [b][h][49][32]
__device__ __half g_aoh[51380224];         // 102.8 MB  attn out fp16 [M][512]

__device__ __forceinline__ void cp_async16(uint32_t dst, const void* src) {
    asm volatile("cp.async.cg.shared.global [%0], [%1], 16;" :: "r"(dst), "l"(src));
}
#define CP_COMMIT() asm volatile("cp.async.commit_group;")
#define CP_WAIT1()  asm volatile("cp.async.wait_group 1;")

#define MMA_F16(c, a, b)                                                      \
    asm volatile("mma.sync.aligned.m16n8k16.row.col.f32.f16.f16.f32 "         \
        "{%0,%1,%2,%3}, {%4,%5,%6,%7}, {%8,%9}, {%0,%1,%2,%3};"               \
        : "+f"((c)[0]), "+f"((c)[1]), "+f"((c)[2]), "+f"((c)[3])              \
        : "r"((a)[0]), "r"((a)[1]), "r"((a)[2]), "r"((a)[3]),                 \
          "r"((b)[0]), "r"((b)[1]))

#define LDSM4(r0, r1, r2, r3, addr)                                           \
    asm volatile("ldmatrix.sync.aligned.m8n8.x4.shared.b16 {%0,%1,%2,%3}, [%4];" \
        : "=r"(r0), "=r"(r1), "=r"(r2), "=r"(r3) : "r"(addr))

// ---------------------------------------------------------------------------
__global__ void prep_w_kernel(const float* __restrict__ qw,
                              const float* __restrict__ qb,
                              const float* __restrict__ pw) {
    int t = blockIdx.x * blockDim.x + threadIdx.x;
    if (t < 512 * 1536) {
        int k  = t / 1536;
        int jn = t - k * 1536;           // jn = s*512 + h*32 + d
        int s  = jn >> 9;
        int r  = jn & 511;
        int h  = r >> 5;
        int d  = r & 31;
        int jo = d * 48 + h * 3 + s;     // source col in (hd, heads, 3) packing
        float v = qw[k * 1536 + jo];
        if (s == 0) v *= SCALE_Q;
        g_wth[jn * 512 + k] = __float2half_rn(v);   // [N][K] n-major
    }
    if (t < 512 * 512) {
        int k = t >> 9;
        int n = t & 511;
        g_pwt[n * 512 + k] = __float2half_rn(pw[t]);
    }
    if (t < 1536) {
        int s = t >> 9;
        int r = t & 511;
        int h = r >> 5;
        int d = r & 31;
        int jo = d * 48 + h * 3 + s;
        float v = qb[jo];
        if (s == 0) v *= SCALE_Q;
        g_bvec[t] = v;
    }
}

// Transpose + fp16-round x: (b, c, n) -> g_xh[(b*49+n)*512 + c]
__global__ __launch_bounds__(256) void prep_xt_kernel(const float* __restrict__ x) {
    __shared__ float s[128][51];
    const int b  = blockIdx.y;
    const int ch = blockIdx.x;            // 0..3
    const int tid = threadIdx.x;
    const float* src = x + (long)b * 25088 + ch * 128 * 49;
    for (int idx = tid; idx < 6272; idx += 256) {
        int c = idx / 49;
        int n = idx - c * 49;
        s[c][n] = src[idx];
    }
    __syncthreads();
    __half* dst = g_xh + (long)b * 25088 + ch * 128;
    for (int idx = tid; idx < 6272; idx += 256) {
        int n = idx >> 7;
        int c = idx & 127;
        dst[(long)n * 512 + c] = __float2half_rn(s[c][n]);
    }
}

__global__ void prep_bm_kernel(const float* __restrict__ mask,
                               const float* __restrict__ table) {
    int t = blockIdx.x * blockDim.x + threadIdx.x;
    if (t >= 64 * 16 * 2401) return;
    int w = t / (16 * 2401);
    int r = t - w * (16 * 2401);
    int h = r / 2401;
    int e = r - h * 2401;
    int n = e / 49;
    int m = e - n * 49;
    int di = n / 7 - m / 7 + 6;
    int dj = (n % 7) - (m % 7) + 6;
    int idx = di * 6 + dj;
    g_bm[t] = table[idx * 16 + h] + mask[w * 2401 + e];
}

// ---------------------------------------------------------------------------
// fp16 GEMM core: block 128x128, K=512 in 8 chunks of 64, 3-stage cp.async,
// ldmatrix fragment loads. smem stage: A[128][72]h + B[128][72]h = 36864 B.
// 8 warps, warp tile 64x32, 4 k-steps of m16n8k16 per chunk.

#define HGEMM_COMPUTE(sbu)                                                    \
    {                                                                         \
        _Pragma("unroll")                                                     \
        for (int ks = 0; ks < 4; ks++) {                                      \
            uint32_t af[4][4], bf[4][2];                                      \
            _Pragma("unroll")                                                 \
            for (int tm = 0; tm < 4; tm++)                                    \
                LDSM4(af[tm][0], af[tm][1], af[tm][2], af[tm][3],             \
                      (sbu) + a_off + tm * 2304 + ks * 32);                   \
            LDSM4(bf[0][0], bf[0][1], bf[1][0], bf[1][1],                     \
                  (sbu) + b_off + ks * 32);                                   \
            LDSM4(bf[2][0], bf[2][1], bf[3][0], bf[3][1],                     \
                  (sbu) + b_off + 2304 + ks * 32);                            \
            _Pragma("unroll")                                                 \
            for (int tm = 0; tm < 4; tm++)                                    \
                _Pragma("unroll")                                             \
                for (int tn = 0; tn < 4; tn++)                                \
                    MMA_F16(acc[tm][tn], af[tm], bf[tn]);                     \
        }                                                                     \
    }

#define HGEMM_PIPE(LOADM)                                                     \
    LOADM(0, 0); CP_COMMIT();                                                 \
    LOADM(1, 1); CP_COMMIT();                                                 \
    {                                                                         \
        int sl = 2, sc = 0;                                                   \
        for (int kc = 0; kc < 8; kc++) {                                      \
            CP_WAIT1();                                                       \
            __syncthreads();                                                  \
            if (kc < 6) LOADM(kc + 2, sl);                                    \
            CP_COMMIT();                                                      \
            HGEMM_COMPUTE(smem_u + sc * 36864);                               \
            sl = (sl == 2) ? 0 : sl + 1;                                      \
            sc = (sc == 2) ? 0 : sc + 1;                                      \
        }                                                                     \
    }

// ldmatrix per-lane byte offsets within a stage:
//  A: rows (wm*64 + lane&15), k-seg (lane>>4)*8 halves
//  B: rows (wn*32 + (lane>>4)*8 + (lane&7)), k-seg ((lane>>3)&1)*8 halves
#define LDSM_OFFS()                                                           \
    const uint32_t a_off = 2u * ((wm * 64 + (lane & 15)) * 72 + (lane >> 4) * 8); \
    const uint32_t b_off = 18432u +                                           \
        2u * ((wn * 32 + (lane >> 4) * 8 + (lane & 7)) * 72 + ((lane >> 3) & 1) * 8);

// QKV GEMM: C[M,1536] = g_xh[M,512] @ g_wth^T + g_bvec -> fp16 q/k/v packed
__global__ __launch_bounds__(256) void gemm_qkv_h() {
    extern __shared__ __align__(16) char smem[];
    const int tid  = threadIdx.x;
    const int lane = tid & 31, warp = tid >> 5;
    const int wm = warp >> 2, wn = warp & 3;
    const int m0 = blockIdx.y << 7;
    const int n0 = blockIdx.x << 7;
    const uint32_t smem_u = (uint32_t)__cvta_generic_to_shared(smem);

    const int r0  = tid >> 3;             // 0..31
    const int c16 = tid & 7;              // 16B segment within 128B row
    const __half* a_src = g_xh  + (long)(m0 + r0) * 512 + c16 * 8;
    const __half* b_src = g_wth + (long)(n0 + r0) * 512 + c16 * 8;
    const uint32_t a_dst = smem_u + r0 * 144 + c16 * 16;
    const uint32_t b_dst = a_dst + 18432;

#define QKV_HLOAD(kc, s)                                                       \
    {                                                                          \
        const __half* ap = a_src + (kc) * 64;                                  \
        uint32_t ad = a_dst + (s) * 36864;                                     \
        _Pragma("unroll")                                                      \
        for (int i = 0; i < 4; i++)                                            \
            cp_async16(ad + i * 4608, ap + i * 16384);                         \
        const __half* bp = b_src + (kc) * 64;                                  \
        uint32_t bd = b_dst + (s) * 36864;                                     \
        _Pragma("unroll")                                                      \
        for (int i = 0; i < 4; i++)                                            \
            cp_async16(bd + i * 4608, bp + i * 16384);                         \
    }

    float acc[4][4][4] = {};
    LDSM_OFFS();

    HGEMM_PIPE(QKV_HLOAD)

    // Epilogue: scatter fp16 into q/k/v [b][h][49][32]
#pragma unroll
    for (int tm = 0; tm < 4; tm++) {
        int r1 = m0 + wm * 64 + tm * 16 + (lane >> 2);
        int r2 = r1 + 8;
        int b1 = r1 / 49, n1 = r1 - b1 * 49;
        int b2 = r2 / 49, n2 = r2 - b2 * 49;
#pragma unroll
        for (int tn = 0; tn < 4; tn++) {
            int cidx = n0 + wn * 32 + tn * 8 + (lane & 3) * 2;
            int s  = cidx >> 9;
            int rh = cidx & 511;
            int hh = rh >> 5;
            int d  = rh & 31;
            __half* dst = (s == 0) ? g_qh : (s == 1) ? g_kh : g_vh;
            float bb0 = g_bvec[cidx], bb1 = g_bvec[cidx + 1];
            *(__half2*)(dst + ((long)(b1 * 16 + hh) * 49 + n1) * 32 + d) =
                __floats2half2_rn(acc[tm][tn][0] + bb0, acc[tm][tn][1] + bb1);
            *(__half2*)(dst + ((long)(b2 * 16 + hh) * 49 + n2) * 32 + d) =
                __floats2half2_rn(acc[tm][tn][2] + bb0, acc[tm][tn][3] + bb1);
        }
    }
}

// ---------------------------------------------------------------------------
// Attention: fp16 smem tiles, fp32 accumulate, 192 threads per (b,h).
__global__ __launch_bounds__(192) void attn_kernel() {
    const int h = blockIdx.x;
    const int b = blockIdx.y;
    const int w = b & 63;
    const int tid = threadIdx.x;

    __shared__ __align__(16) __half sq[52][40];
    __shared__ __align__(16) __half sk[52][40];
    __shared__ __align__(16) __half sv[49][40];
    __shared__ float sS[52][53];
    __shared__ float sinv[49];

    const long tb = (long)(b * 16 + h) * 49 * 32;
    const uint4* qsrc = (const uint4*)(g_qh + tb);
    const uint4* ksrc = (const uint4*)(g_kh + tb);
    const uint4* vsrc = (const uint4*)(g_vh + tb);
    for (int t = tid; t < 196; t += 192) {       // 49 rows x 4 uint4 (32 halves)
        int row = t >> 2, seg = (t & 3) * 8;
        *(uint4*)&sq[row][seg] = qsrc[t];
        *(uint4*)&sk[row][seg] = ksrc[t];
        *(uint4*)&sv[row][seg] = vsrc[t];
    }
    if (tid < 24) {                               // zero pad rows 49..51 of q,k
        int tsel = tid / 12, idx = tid - tsel * 12;
        int row = 49 + (idx >> 2), seg = (idx & 3) * 8;
        uint4 z = {0u, 0u, 0u, 0u};
        if (tsel == 0) *(uint4*)&sq[row][seg] = z;
        else           *(uint4*)&sk[row][seg] = z;
    }
    const float* bm = g_bm + (w * 16 + h) * 2401;
    for (int e = tid; e < 2401; e += 192) {
        int i = e / 49;
        int j = e - i * 49;
        sS[i][j] = bm[e];
    }
    __syncthreads();

    if (tid < 169) {
        int ti = tid / 13, tj = tid - ti * 13;
        int i0 = ti * 4, j0 = tj * 4;
        float acc[4][4] = {};
#pragma unroll
        for (int d8 = 0; d8 < 4; d8++) {
            float qf[4][8], kf[4][8];
#pragma unroll
            for (int r = 0; r < 4; r++) {
                uint4 u = *(uint4*)&sq[i0 + r][d8 * 8];
                float2 f0 = __half22float2(*(__half2*)&u.x);
                float2 f1 = __half22float2(*(__half2*)&u.y);
                float2 f2 = __half22float2(*(__half2*)&u.z);
                float2 f3 = __half22float2(*(__half2*)&u.w);
                qf[r][0] = f0.x; qf[r][1] = f0.y; qf[r][2] = f1.x; qf[r][3] = f1.y;
                qf[r][4] = f2.x; qf[r][5] = f2.y; qf[r][6] = f3.x; qf[r][7] = f3.y;
            }
#pragma unroll
            for (int r = 0; r < 4; r++) {
                uint4 u = *(uint4*)&sk[j0 + r][d8 * 8];
                float2 f0 = __half22float2(*(__half2*)&u.x);
                float2 f1 = __half22float2(*(__half2*)&u.y);
                float2 f2 = __half22float2(*(__half2*)&u.z);
                float2 f3 = __half22float2(*(__half2*)&u.w);
                kf[r][0] = f0.x; kf[r][1] = f0.y; kf[r][2] = f1.x; kf[r][3] = f1.y;
                kf[r][4] = f2.x; kf[r][5] = f2.y; kf[r][6] = f3.x; kf[r][7] = f3.y;
            }
#pragma unroll
            for (int r = 0; r < 4; r++)
#pragma unroll
                for (int cc = 0; cc < 4; cc++)
#pragma unroll
                    for (int e = 0; e < 8; e++)
                        acc[r][cc] = fmaf(qf[r][e], kf[cc][e], acc[r][cc]);
        }
#pragma unroll
        for (int r = 0; r < 4; r++)
            if (i0 + r < 49)
#pragma unroll
                for (int cc = 0; cc < 4; cc++)
                    if (j0 + cc < 49)
                        sS[i0 + r][j0 + cc] += acc[r][cc];
    }
    __syncthreads();

    if (tid < 49) {
        float mx = -1e30f;
#pragma unroll
        for (int j = 0; j < 49; j++) mx = fmaxf(mx, sS[tid][j]);
        float s = 0.f;
#pragma unroll
        for (int j = 0; j < 49; j++) {
            float p = __expf(sS[tid][j] - mx);
            sS[tid][j] = p;
            s += p;
        }
        sinv[tid] = 1.0f / s;
    }
    __syncthreads();

    if (tid < 104) {
        int ti = tid >> 3, td = tid & 7;
        int i0 = ti * 4, d0 = td * 4;
        float acc[4][4] = {};
        for (int j = 0; j < 49; j++) {
            uint32_t v0 = *(uint32_t*)&sv[j][d0];
            uint32_t v1 = *(uint32_t*)&sv[j][d0 + 2];
            float2 va = __half22float2(*(__half2*)&v0);
            float2 vb = __half22float2(*(__half2*)&v1);
#pragma unroll
            for (int r = 0; r < 4; r++) {
                float p = sS[i0 + r][j];
                acc[r][0] = fmaf(p, va.x, acc[r][0]);
                acc[r][1] = fmaf(p, va.y, acc[r][1]);
                acc[r][2] = fmaf(p, vb.x, acc[r][2]);
                acc[r][3] = fmaf(p, vb.y, acc[r][3]);
            }
        }
        __half* ob = g_aoh + (long)b * 25088 + h * 32 + d0;
#pragma unroll
        for (int r = 0; r < 4; r++) {
            int i = i0 + r;
            if (i < 49) {
                float si = sinv[i];
                __half2* op = (__half2*)(ob + (long)i * 512);
                op[0] = __floats2half2_rn(acc[r][0] * si, acc[r][1] * si);
                op[1] = __floats2half2_rn(acc[r][2] * si, acc[r][3] * si);
            }
        }
    }
}

// ---------------------------------------------------------------------------
// Proj GEMM (fp16 HMMA + ldmatrix): Y = g_aoh @ g_pwt^T + proj_b, transposed out.
__global__ __launch_bounds__(256) void gemm_proj_h(const float* __restrict__ pb,
                                                   float* __restrict__ out) {
    extern __shared__ __align__(16) char smem[];
    float* smf = (float*)smem;
    const int tid  = threadIdx.x;
    const int lane = tid & 31, warp = tid >> 5;
    const int wm = warp >> 2, wn = warp & 3;
    const int m0 = blockIdx.y << 7;
    const int n0 = blockIdx.x << 7;
    const uint32_t smem_u = (uint32_t)__cvta_generic_to_shared(smem);

    const int r0  = tid >> 3;
    const int c16 = tid & 7;
    const __half* a_src = g_aoh + (long)(m0 + r0) * 512 + c16 * 8;
    const __half* b_src = g_pwt + (long)(n0 + r0) * 512 + c16 * 8;
    const uint32_t a_dst = smem_u + r0 * 144 + c16 * 16;
    const uint32_t b_dst = a_dst + 18432;

#define PROJ_HLOAD(kc, s)                                                      \
    {                                                                          \
        const __half* ap = a_src + (kc) * 64;                                  \
        uint32_t ad = a_dst + (s) * 36864;                                     \
        _Pragma("unroll")                                                      \
        for (int i = 0; i < 4; i++)                                            \
            cp_async16(ad + i * 4608, ap + i * 16384);                         \
        const __half* bp = b_src + (kc) * 64;                                  \
        uint32_t bd = b_dst + (s) * 36864;                                     \
        _Pragma("unroll")                                                      \
        for (int i = 0; i < 4; i++)                                            \
            cp_async16(bd + i * 4608, bp + i * 16384);                         \
    }

    float acc[4][4][4] = {};
    LDSM_OFFS();

    HGEMM_PIPE(PROJ_HLOAD)

    // Transposed epilogue via smem staging, two 64-column halves.
    float* stg = smf;                      // [128][66]
    const int r_l  = tid & 127;
    int rowg = m0 + r_l;
    int ob_b = rowg / 49;
    int ob_n = rowg - ob_b * 49;
    float* obase = out + (long)ob_b * 25088 + ob_n;
    const int ccb = tid >> 7;

    for (int half = 0; half < 2; half++) {
        __syncthreads();
        if ((wn >> 1) == half) {
#pragma unroll
            for (int tm = 0; tm < 4; tm++) {
                int rl = wm * 64 + tm * 16 + (lane >> 2);
#pragma unroll
                for (int tn = 0; tn < 4; tn++) {
                    int cl = (wn & 1) * 32 + tn * 8 + (lane & 3) * 2;
                    int cg = n0 + half * 64 + cl;
                    float b0 = pb[cg], b1 = pb[cg + 1];
                    stg[rl * 66 + cl]           = acc[tm][tn][0] + b0;
                    stg[rl * 66 + cl + 1]       = acc[tm][tn][1] + b1;
                    stg[(rl + 8) * 66 + cl]     = acc[tm][tn][2] + b0;
                    stg[(rl + 8) * 66 + cl + 1] = acc[tm][tn][3] + b1;
                }
            }
        }
        __syncthreads();
#pragma unroll
        for (int i = 0; i < 32; i++) {
            int cc = ccb + 2 * i;
            int ch = n0 + half * 64 + cc;
            obase[(long)ch * 49] = stg[r_l * 66 + cc];
        }
    }
}

// ---------------------------------------------------------------------------
extern "C" void kernel_launch(void* const* d_in, const int* in_sizes, int n_in,
                              void* d_out, int out_size) {
    const float *x = nullptr, *mask = nullptr, *table = nullptr;
    const float *qw = nullptr, *qb = nullptr, *pw = nullptr, *pb = nullptr;
    for (int i = 0; i < n_in; i++) {
        const float* p = (const float*)d_in[i];
        switch (in_sizes[i]) {
            case 51380224: x = p; break;
            case 153664:   mask = p; break;
            case 2704:     table = p; break;
            case 786432:   qw = p; break;
            case 1536:     qb = p; break;
            case 262144:   pw = p; break;
            case 512:      pb = p; break;
        }
    }
    float* out = (float*)d_out;

    const int gemm_smem = 110592;   // 3 stages * 36864 B
    cudaFuncSetAttribute(gemm_qkv_h,  cudaFuncAttributeMaxDynamicSharedMemorySize, gemm_smem);
    cudaFuncSetAttribute(gemm_proj_h, cudaFuncAttributeMaxDynamicSharedMemorySize, gemm_smem);

    prep_w_kernel<<<(512 * 1536 + 255) / 256, 256>>>(qw, qb, pw);
    prep_bm_kernel<<<(64 * 16 * 2401 + 255) / 256, 256>>>(mask, table);
    prep_xt_kernel<<<dim3(4, 2048), 256>>>(x);
    gemm_qkv_h<<<dim3(12, 784), 256, gemm_smem>>>();
    attn_kernel<<<dim3(16, 2048), 192>>>();
    gemm_proj_h<<<dim3(4, 784), 256, gemm_smem>>>(pb, out);
}

// round 7
// speedup vs baseline: 4.3605x; 1.0577x over previous
#include <cuda_runtime.h>
#include <cuda_fp16.h>
#include <cstdint>

// ---------------------------------------------------------------------------
// WindowAttention: x(2048,512,7,7) -> out(2048,512,7,7)
// bs=2048, c=512, ws=7, N=49, H=16, hd=32, n_windows=64, M=bs*N=100352
// Round 7: rebalanced 256-thread attention (parallel softmax, no max pass,
//          4x3 QK tiles, 2-col PV tiles). GEMMs unchanged from round 6.
// ---------------------------------------------------------------------------

#define SCALE_Q 0.17677669529663687f   // 32^-0.5

__device__ __half g_wth[1536 * 512];       //   1.5 MB  qkv weight [N][K], fp16
__device__ __half g_pwt[512 * 512];        //   0.5 MB  proj weight [N][K], fp16
__device__ float  g_bvec[1536];            //           permuted qkv bias (exact)
__device__ float  g_bm[64 * 16 * 2401];    //   9.8 MB  fused bias+mask
__device__ __half g_xh[51380224];          // 102.8 MB  fp16 transposed x: [M][512]
__device__ __half g_qh[51380224];          // 102.8 MB  q fp16 [b][h][49][32]
__device__ __half g_kh[51380224];          // 102.8 MB  k fp16 [b][h][49][32]
__device__ __half g_vh[51380224];          // 102.8 MB  v fp16 [b][h][49][32]
__device__ __half g_aoh[51380224];         // 102.8 MB  attn out fp16 [M][512]

__device__ __forceinline__ void cp_async16(uint32_t dst, const void* src) {
    asm volatile("cp.async.cg.shared.global [%0], [%1], 16;" :: "r"(dst), "l"(src));
}
#define CP_COMMIT() asm volatile("cp.async.commit_group;")
#define CP_WAIT1()  asm volatile("cp.async.wait_group 1;")

#define MMA_F16(c, a, b)                                                      \
    asm volatile("mma.sync.aligned.m16n8k16.row.col.f32.f16.f16.f32 "         \
        "{%0,%1,%2,%3}, {%4,%5,%6,%7}, {%8,%9}, {%0,%1,%2,%3};"               \
        : "+f"((c)[0]), "+f"((c)[1]), "+f"((c)[2]), "+f"((c)[3])              \
        : "r"((a)[0]), "r"((a)[1]), "r"((a)[2]), "r"((a)[3]),                 \
          "r"((b)[0]), "r"((b)[1]))

#define LDSM4(r0, r1, r2, r3, addr)                                           \
    asm volatile("ldmatrix.sync.aligned.m8n8.x4.shared.b16 {%0,%1,%2,%3}, [%4];" \
        : "=r"(r0), "=r"(r1), "=r"(r2), "=r"(r3) : "r"(addr))

// ---------------------------------------------------------------------------
__global__ void prep_w_kernel(const float* __restrict__ qw,
                              const float* __restrict__ qb,
                              const float* __restrict__ pw) {
    int t = blockIdx.x * blockDim.x + threadIdx.x;
    if (t < 512 * 1536) {
        int k  = t / 1536;
        int jn = t - k * 1536;           // jn = s*512 + h*32 + d
        int s  = jn >> 9;
        int r  = jn & 511;
        int h  = r >> 5;
        int d  = r & 31;
        int jo = d * 48 + h * 3 + s;     // source col in (hd, heads, 3) packing
        float v = qw[k * 1536 + jo];
        if (s == 0) v *= SCALE_Q;
        g_wth[jn * 512 + k] = __float2half_rn(v);   // [N][K] n-major
    }
    if (t < 512 * 512) {
        int k = t >> 9;
        int n = t & 511;
        g_pwt[n * 512 + k] = __float2half_rn(pw[t]);
    }
    if (t < 1536) {
        int s = t >> 9;
        int r = t & 511;
        int h = r >> 5;
        int d = r & 31;
        int jo = d * 48 + h * 3 + s;
        float v = qb[jo];
        if (s == 0) v *= SCALE_Q;
        g_bvec[t] = v;
    }
}

// Transpose + fp16-round x: (b, c, n) -> g_xh[(b*49+n)*512 + c]
__global__ __launch_bounds__(256) void prep_xt_kernel(const float* __restrict__ x) {
    __shared__ float s[128][51];
    const int b  = blockIdx.y;
    const int ch = blockIdx.x;            // 0..3
    const int tid = threadIdx.x;
    const float* src = x + (long)b * 25088 + ch * 128 * 49;
    for (int idx = tid; idx < 6272; idx += 256) {
        int c = idx / 49;
        int n = idx - c * 49;
        s[c][n] = src[idx];
    }
    __syncthreads();
    __half* dst = g_xh + (long)b * 25088 + ch * 128;
    for (int idx = tid; idx < 6272; idx += 256) {
        int n = idx >> 7;
        int c = idx & 127;
        dst[(long)n * 512 + c] = __float2half_rn(s[c][n]);
    }
}

__global__ void prep_bm_kernel(const float* __restrict__ mask,
                               const float* __restrict__ table) {
    int t = blockIdx.x * blockDim.x + threadIdx.x;
    if (t >= 64 * 16 * 2401) return;
    int w = t / (16 * 2401);
    int r = t - w * (16 * 2401);
    int h = r / 2401;
    int e = r - h * 2401;
    int n = e / 49;
    int m = e - n * 49;
    int di = n / 7 - m / 7 + 6;
    int dj = (n % 7) - (m % 7) + 6;
    int idx = di * 6 + dj;
    g_bm[t] = table[idx * 16 + h] + mask[w * 2401 + e];
}

// ---------------------------------------------------------------------------
// fp16 GEMM core (unchanged from round 6): block 128x128, 8 chunks of 64,
// 3-stage cp.async, ldmatrix fragment loads.

#define HGEMM_COMPUTE(sbu)                                                    \
    {                                                                         \
        _Pragma("unroll")                                                     \
        for (int ks = 0; ks < 4; ks++) {                                      \
            uint32_t af[4][4], bf[4][2];                                      \
            _Pragma("unroll")                                                 \
            for (int tm = 0; tm < 4; tm++)                                    \
                LDSM4(af[tm][0], af[tm][1], af[tm][2], af[tm][3],             \
                      (sbu) + a_off + tm * 2304 + ks * 32);                   \
            LDSM4(bf[0][0], bf[0][1], bf[1][0], bf[1][1],                     \
                  (sbu) + b_off + ks * 32);                                   \
            LDSM4(bf[2][0], bf[2][1], bf[3][0], bf[3][1],                     \
                  (sbu) + b_off + 2304 + ks * 32);                            \
            _Pragma("unroll")                                                 \
            for (int tm = 0; tm < 4; tm++)                                    \
                _Pragma("unroll")                                             \
                for (int tn = 0; tn < 4; tn++)                                \
                    MMA_F16(acc[tm][tn], af[tm], bf[tn]);                     \
        }                                                                     \
    }

#define HGEMM_PIPE(LOADM)                                                     \
    LOADM(0, 0); CP_COMMIT();                                                 \
    LOADM(1, 1); CP_COMMIT();                                                 \
    {                                                                         \
        int sl = 2, sc = 0;                                                   \
        for (int kc = 0; kc < 8; kc++) {                                      \
            CP_WAIT1();                                                       \
            __syncthreads();                                                  \
            if (kc < 6) LOADM(kc + 2, sl);                                    \
            CP_COMMIT();                                                      \
            HGEMM_COMPUTE(smem_u + sc * 36864);                               \
            sl = (sl == 2) ? 0 : sl + 1;                                      \
            sc = (sc == 2) ? 0 : sc + 1;                                      \
        }                                                                     \
    }

#define LDSM_OFFS()                                                           \
    const uint32_t a_off = 2u * ((wm * 64 + (lane & 15)) * 72 + (lane >> 4) * 8); \
    const uint32_t b_off = 18432u +                                           \
        2u * ((wn * 32 + (lane >> 4) * 8 + (lane & 7)) * 72 + ((lane >> 3) & 1) * 8);

// QKV GEMM: C[M,1536] = g_xh[M,512] @ g_wth^T + g_bvec -> fp16 q/k/v packed
__global__ __launch_bounds__(256) void gemm_qkv_h() {
    extern __shared__ __align__(16) char smem[];
    const int tid  = threadIdx.x;
    const int lane = tid & 31, warp = tid >> 5;
    const int wm = warp >> 2, wn = warp & 3;
    const int m0 = blockIdx.y << 7;
    const int n0 = blockIdx.x << 7;
    const uint32_t smem_u = (uint32_t)__cvta_generic_to_shared(smem);

    const int r0  = tid >> 3;             // 0..31
    const int c16 = tid & 7;              // 16B segment within 128B row
    const __half* a_src = g_xh  + (long)(m0 + r0) * 512 + c16 * 8;
    const __half* b_src = g_wth + (long)(n0 + r0) * 512 + c16 * 8;
    const uint32_t a_dst = smem_u + r0 * 144 + c16 * 16;
    const uint32_t b_dst = a_dst + 18432;

#define QKV_HLOAD(kc, s)                                                       \
    {                                                                          \
        const __half* ap = a_src + (kc) * 64;                                  \
        uint32_t ad = a_dst + (s) * 36864;                                     \
        _Pragma("unroll")                                                      \
        for (int i = 0; i < 4; i++)                                            \
            cp_async16(ad + i * 4608, ap + i * 16384);                         \
        const __half* bp = b_src + (kc) * 64;                                  \
        uint32_t bd = b_dst + (s) * 36864;                                     \
        _Pragma("unroll")                                                      \
        for (int i = 0; i < 4; i++)                                            \
            cp_async16(bd + i * 4608, bp + i * 16384);                         \
    }

    float acc[4][4][4] = {};
    LDSM_OFFS();

    HGEMM_PIPE(QKV_HLOAD)

    // Epilogue: scatter fp16 into q/k/v [b][h][49][32]
#pragma unroll
    for (int tm = 0; tm < 4; tm++) {
        int r1 = m0 + wm * 64 + tm * 16 + (lane >> 2);
        int r2 = r1 + 8;
        int b1 = r1 / 49, n1 = r1 - b1 * 49;
        int b2 = r2 / 49, n2 = r2 - b2 * 49;
#pragma unroll
        for (int tn = 0; tn < 4; tn++) {
            int cidx = n0 + wn * 32 + tn * 8 + (lane & 3) * 2;
            int s  = cidx >> 9;
            int rh = cidx & 511;
            int hh = rh >> 5;
            int d  = rh & 31;
            __half* dst = (s == 0) ? g_qh : (s == 1) ? g_kh : g_vh;
            float bb0 = g_bvec[cidx], bb1 = g_bvec[cidx + 1];
            *(__half2*)(dst + ((long)(b1 * 16 + hh) * 49 + n1) * 32 + d) =
                __floats2half2_rn(acc[tm][tn][0] + bb0, acc[tm][tn][1] + bb1);
            *(__half2*)(dst + ((long)(b2 * 16 + hh) * 49 + n2) * 32 + d) =
                __floats2half2_rn(acc[tm][tn][2] + bb0, acc[tm][tn][3] + bb1);
        }
    }
}

// ---------------------------------------------------------------------------
// Attention: 256 threads per (b,h). fp16 smem tiles, fp32 accumulate.
// Phases: QK 4x3 tiles (221 thr) -> parallel softmax (196 thr, no max pass)
//         -> PV 4 rows x 2 cols (208 thr).
__global__ __launch_bounds__(256) void attn_kernel() {
    const int h = blockIdx.x;
    const int b = blockIdx.y;
    const int w = b & 63;
    const int tid = threadIdx.x;

    __shared__ __align__(16) __half sq[52][40];
    __shared__ __align__(16) __half sk[52][40];
    __shared__ __align__(16) __half sv[49][40];
    __shared__ float sS[52][53];
    __shared__ float spart[49][4];
    __shared__ float sinv[49];

    const long tb = (long)(b * 16 + h) * 49 * 32;
    const uint4* qsrc = (const uint4*)(g_qh + tb);
    const uint4* ksrc = (const uint4*)(g_kh + tb);
    const uint4* vsrc = (const uint4*)(g_vh + tb);
    if (tid < 196) {                              // 49 rows x 4 uint4 each
        int row = tid >> 2, seg = (tid & 3) * 8;
        *(uint4*)&sq[row][seg] = qsrc[tid];
        *(uint4*)&sk[row][seg] = ksrc[tid];
        *(uint4*)&sv[row][seg] = vsrc[tid];
    } else if (tid < 220) {                       // zero pad rows 49..51 of q,k
        int t = tid - 196;
        int tsel = t / 12, idx = t - tsel * 12;
        int row = 49 + (idx >> 2), seg = (idx & 3) * 8;
        uint4 z = {0u, 0u, 0u, 0u};
        if (tsel == 0) *(uint4*)&sq[row][seg] = z;
        else           *(uint4*)&sk[row][seg] = z;
    }
    const float* bm = g_bm + (w * 16 + h) * 2401;
    for (int e = tid; e < 2401; e += 256) {
        int i = e / 49;
        int j = e - i * 49;
        sS[i][j] = bm[e];
    }
    __syncthreads();

    // QK: 13 i-tiles (4 rows) x 17 j-tiles (3 cols) = 221 threads
    if (tid < 221) {
        int ti = tid / 17, tj = tid - ti * 17;
        int i0 = ti * 4, j0 = tj * 3;
        float acc[4][3] = {};
#pragma unroll
        for (int d8 = 0; d8 < 4; d8++) {
            float qf[4][8], kf[3][8];
#pragma unroll
            for (int r = 0; r < 4; r++) {
                uint4 u = *(uint4*)&sq[i0 + r][d8 * 8];
                float2 f0 = __half22float2(*(__half2*)&u.x);
                float2 f1 = __half22float2(*(__half2*)&u.y);
                float2 f2 = __half22float2(*(__half2*)&u.z);
                float2 f3 = __half22float2(*(__half2*)&u.w);
                qf[r][0] = f0.x; qf[r][1] = f0.y; qf[r][2] = f1.x; qf[r][3] = f1.y;
                qf[r][4] = f2.x; qf[r][5] = f2.y; qf[r][6] = f3.x; qf[r][7] = f3.y;
            }
#pragma unroll
            for (int cc = 0; cc < 3; cc++) {
                uint4 u = *(uint4*)&sk[j0 + cc][d8 * 8];
                float2 f0 = __half22float2(*(__half2*)&u.x);
                float2 f1 = __half22float2(*(__half2*)&u.y);
                float2 f2 = __half22float2(*(__half2*)&u.z);
                float2 f3 = __half22float2(*(__half2*)&u.w);
                kf[cc][0] = f0.x; kf[cc][1] = f0.y; kf[cc][2] = f1.x; kf[cc][3] = f1.y;
                kf[cc][4] = f2.x; kf[cc][5] = f2.y; kf[cc][6] = f3.x; kf[cc][7] = f3.y;
            }
#pragma unroll
            for (int r = 0; r < 4; r++)
#pragma unroll
                for (int cc = 0; cc < 3; cc++)
#pragma unroll
                    for (int e = 0; e < 8; e++)
                        acc[r][cc] = fmaf(qf[r][e], kf[cc][e], acc[r][cc]);
        }
#pragma unroll
        for (int r = 0; r < 4; r++)
            if (i0 + r < 49)
#pragma unroll
                for (int cc = 0; cc < 3; cc++)
                    if (j0 + cc < 49)
                        sS[i0 + r][j0 + cc] += acc[r][cc];
    }
    __syncthreads();

    // Parallel softmax (no max subtraction; scores are O(10), fp32-safe):
    // 4 threads per row, 13-col strips. exp in-place, partial sums to spart.
    if (tid < 196) {
        int row = tid >> 2, q = tid & 3;
        int c0 = q * 13;
        int c1 = (q == 3) ? 49 : c0 + 13;
        float s = 0.f;
        for (int c = c0; c < c1; c++) {
            float p = __expf(sS[row][c]);
            sS[row][c] = p;
            s += p;
        }
        spart[row][q] = s;
    }
    __syncthreads();
    if (tid < 49)
        sinv[tid] = 1.0f / (spart[tid][0] + spart[tid][1] +
                            spart[tid][2] + spart[tid][3]);
    __syncthreads();

    // PV: 13 i-tiles (4 rows) x 16 d-pairs = 208 threads
    if (tid < 208) {
        int ti = tid >> 4, td = tid & 15;
        int i0 = ti * 4, d0 = td * 2;
        float acc[4][2] = {};
        for (int j = 0; j < 49; j++) {
            uint32_t v = *(uint32_t*)&sv[j][d0];
            float2 vf = __half22float2(*(__half2*)&v);
#pragma unroll
            for (int r = 0; r < 4; r++) {
                float p = sS[i0 + r][j];
                acc[r][0] = fmaf(p, vf.x, acc[r][0]);
                acc[r][1] = fmaf(p, vf.y, acc[r][1]);
            }
        }
        __half* ob = g_aoh + (long)b * 25088 + h * 32 + d0;
#pragma unroll
        for (int r = 0; r < 4; r++) {
            int i = i0 + r;
            if (i < 49) {
                float si = sinv[i];
                *(__half2*)(ob + (long)i * 512) =
                    __floats2half2_rn(acc[r][0] * si, acc[r][1] * si);
            }
        }
    }
}

// ---------------------------------------------------------------------------
// Proj GEMM (fp16 HMMA + ldmatrix, unchanged): Y = g_aoh @ g_pwt^T + proj_b.
__global__ __launch_bounds__(256) void gemm_proj_h(const float* __restrict__ pb,
                                                   float* __restrict__ out) {
    extern __shared__ __align__(16) char smem[];
    float* smf = (float*)smem;
    const int tid  = threadIdx.x;
    const int lane = tid & 31, warp = tid >> 5;
    const int wm = warp >> 2, wn = warp & 3;
    const int m0 = blockIdx.y << 7;
    const int n0 = blockIdx.x << 7;
    const uint32_t smem_u = (uint32_t)__cvta_generic_to_shared(smem);

    const int r0  = tid >> 3;
    const int c16 = tid & 7;
    const __half* a_src = g_aoh + (long)(m0 + r0) * 512 + c16 * 8;
    const __half* b_src = g_pwt + (long)(n0 + r0) * 512 + c16 * 8;
    const uint32_t a_dst = smem_u + r0 * 144 + c16 * 16;
    const uint32_t b_dst = a_dst + 18432;

#define PROJ_HLOAD(kc, s)                                                      \
    {                                                                          \
        const __half* ap = a_src + (kc) * 64;                                  \
        uint32_t ad = a_dst + (s) * 36864;                                     \
        _Pragma("unroll")                                                      \
        for (int i = 0; i < 4; i++)                                            \
            cp_async16(ad + i * 4608, ap + i * 16384);                         \
        const __half* bp = b_src + (kc) * 64;                                  \
        uint32_t bd = b_dst + (s) * 36864;                                     \
        _Pragma("unroll")                                                      \
        for (int i = 0; i < 4; i++)                                            \
            cp_async16(bd + i * 4608, bp + i * 16384);                         \
    }

    float acc[4][4][4] = {};
    LDSM_OFFS();

    HGEMM_PIPE(PROJ_HLOAD)

    // Transposed epilogue via smem staging, two 64-column halves.
    float* stg = smf;                      // [128][66]
    const int r_l  = tid & 127;
    int rowg = m0 + r_l;
    int ob_b = rowg / 49;
    int ob_n = rowg - ob_b * 49;
    float* obase = out + (long)ob_b * 25088 + ob_n;
    const int ccb = tid >> 7;

    for (int half = 0; half < 2; half++) {
        __syncthreads();
        if ((wn >> 1) == half) {
#pragma unroll
            for (int tm = 0; tm < 4; tm++) {
                int rl = wm * 64 + tm * 16 + (lane >> 2);
#pragma unroll
                for (int tn = 0; tn < 4; tn++) {
                    int cl = (wn & 1) * 32 + tn * 8 + (lane & 3) * 2;
                    int cg = n0 + half * 64 + cl;
                    float b0 = pb[cg], b1 = pb[cg + 1];
                    stg[rl * 66 + cl]           = acc[tm][tn][0] + b0;
                    stg[rl * 66 + cl + 1]       = acc[tm][tn][1] + b1;
                    stg[(rl + 8) * 66 + cl]     = acc[tm][tn][2] + b0;
                    stg[(rl + 8) * 66 + cl + 1] = acc[tm][tn][3] + b1;
                }
            }
        }
        __syncthreads();
#pragma unroll
        for (int i = 0; i < 32; i++) {
            int cc = ccb + 2 * i;
            int ch = n0 + half * 64 + cc;
            obase[(long)ch * 49] = stg[r_l * 66 + cc];
        }
    }
}

// ---------------------------------------------------------------------------
extern "C" void kernel_launch(void* const* d_in, const int* in_sizes, int n_in,
                              void* d_out, int out_size) {
    const float *x = nullptr, *mask = nullptr, *table = nullptr;
    const float *qw = nullptr, *qb = nullptr, *pw = nullptr, *pb = nullptr;
    for (int i = 0; i < n_in; i++) {
        const float* p = (const float*)d_in[i];
        switch (in_sizes[i]) {
            case 51380224: x = p; break;
            case 153664:   mask = p; break;
            case 2704:     table = p; break;
            case 786432:   qw = p; break;
            case 1536:     qb = p; break;
            case 262144:   pw = p; break;
            case 512:      pb = p; break;
        }
    }
    float* out = (float*)d_out;

    const int gemm_smem = 110592;   // 3 stages * 36864 B
    cudaFuncSetAttribute(gemm_qkv_h,  cudaFuncAttributeMaxDynamicSharedMemorySize, gemm_smem);
    cudaFuncSetAttribute(gemm_proj_h, cudaFuncAttributeMaxDynamicSharedMemorySize, gemm_smem);

    prep_w_kernel<<<(512 * 1536 + 255) / 256, 256>>>(qw, qb, pw);
    prep_bm_kernel<<<(64 * 16 * 2401 + 255) / 256, 256>>>(mask, table);
    prep_xt_kernel<<<dim3(4, 2048), 256>>>(x);
    gemm_qkv_h<<<dim3(12, 784), 256, gemm_smem>>>();
    attn_kernel<<<dim3(16, 2048), 256>>>();
    gemm_proj_h<<<dim3(4, 784), 256, gemm_smem>>>(pb, out);
}

// round 8
// speedup vs baseline: 5.8659x; 1.3452x over previous
#include <cuda_runtime.h>
#include <cuda_fp16.h>
#include <cstdint>

// ---------------------------------------------------------------------------
// WindowAttention: x(2048,512,7,7) -> out(2048,512,7,7)
// bs=2048, c=512, ws=7, N=49, H=16, hd=32, n_windows=64, M=bs*N=100352
// Round 8: HMMA flash-style attention (QK + PV on tensor cores, P in
//          registers, V pre-transposed). GEMMs unchanged from round 6/7.
// ---------------------------------------------------------------------------

#define SCALE_Q 0.17677669529663687f   // 32^-0.5

__device__ __half g_wth[1536 * 512];       //   1.5 MB  qkv weight [N][K], fp16
__device__ __half g_pwt[512 * 512];        //   0.5 MB  proj weight [N][K], fp16
__device__ float  g_bvec[1536];            //           permuted qkv bias (exact)
__device__ float  g_bm[64 * 16 * 2401];    //   9.8 MB  fused bias+mask
__device__ __half g_xh[51380224];          // 102.8 MB  fp16 transposed x: [M][512]
__device__ __half g_qh[51380224];          // 102.8 MB  q fp16 [b][h][49][32]
__device__ __half g_kh[51380224];          // 102.8 MB  k fp16 [b][h][49][32]
__device__ __half g_vt[67108864];          // 128.0 MB  v^T fp16 [b][h][32][64] (pad 0)
__device__ __half g_aoh[51380224];         // 102.8 MB  attn out fp16 [M][512]

__device__ __forceinline__ void cp_async16(uint32_t dst, const void* src) {
    asm volatile("cp.async.cg.shared.global [%0], [%1], 16;" :: "r"(dst), "l"(src));
}
#define CP_COMMIT() asm volatile("cp.async.commit_group;")
#define CP_WAIT1()  asm volatile("cp.async.wait_group 1;")

#define MMA_F16(c, a, b)                                                      \
    asm volatile("mma.sync.aligned.m16n8k16.row.col.f32.f16.f16.f32 "         \
        "{%0,%1,%2,%3}, {%4,%5,%6,%7}, {%8,%9}, {%0,%1,%2,%3};"               \
        : "+f"((c)[0]), "+f"((c)[1]), "+f"((c)[2]), "+f"((c)[3])              \
        : "r"((a)[0]), "r"((a)[1]), "r"((a)[2]), "r"((a)[3]),                 \
          "r"((b)[0]), "r"((b)[1]))

#define LDSM4(r0, r1, r2, r3, addr)                                           \
    asm volatile("ldmatrix.sync.aligned.m8n8.x4.shared.b16 {%0,%1,%2,%3}, [%4];" \
        : "=r"(r0), "=r"(r1), "=r"(r2), "=r"(r3) : "r"(addr))

// ---------------------------------------------------------------------------
__global__ void prep_w_kernel(const float* __restrict__ qw,
                              const float* __restrict__ qb,
                              const float* __restrict__ pw) {
    int t = blockIdx.x * blockDim.x + threadIdx.x;
    if (t < 512 * 1536) {
        int k  = t / 1536;
        int jn = t - k * 1536;           // jn = s*512 + h*32 + d
        int s  = jn >> 9;
        int r  = jn & 511;
        int h  = r >> 5;
        int d  = r & 31;
        int jo = d * 48 + h * 3 + s;     // source col in (hd, heads, 3) packing
        float v = qw[k * 1536 + jo];
        if (s == 0) v *= SCALE_Q;
        g_wth[jn * 512 + k] = __float2half_rn(v);   // [N][K] n-major
    }
    if (t < 512 * 512) {
        int k = t >> 9;
        int n = t & 511;
        g_pwt[n * 512 + k] = __float2half_rn(pw[t]);
    }
    if (t < 1536) {
        int s = t >> 9;
        int r = t & 511;
        int h = r >> 5;
        int d = r & 31;
        int jo = d * 48 + h * 3 + s;
        float v = qb[jo];
        if (s == 0) v *= SCALE_Q;
        g_bvec[t] = v;
    }
}

// Transpose + fp16-round x: (b, c, n) -> g_xh[(b*49+n)*512 + c]
__global__ __launch_bounds__(256) void prep_xt_kernel(const float* __restrict__ x) {
    __shared__ float s[128][51];
    const int b  = blockIdx.y;
    const int ch = blockIdx.x;            // 0..3
    const int tid = threadIdx.x;
    const float* src = x + (long)b * 25088 + ch * 128 * 49;
    for (int idx = tid; idx < 6272; idx += 256) {
        int c = idx / 49;
        int n = idx - c * 49;
        s[c][n] = src[idx];
    }
    __syncthreads();
    __half* dst = g_xh + (long)b * 25088 + ch * 128;
    for (int idx = tid; idx < 6272; idx += 256) {
        int n = idx >> 7;
        int c = idx & 127;
        dst[(long)n * 512 + c] = __float2half_rn(s[c][n]);
    }
}

__global__ void prep_bm_kernel(const float* __restrict__ mask,
                               const float* __restrict__ table) {
    int t = blockIdx.x * blockDim.x + threadIdx.x;
    if (t >= 64 * 16 * 2401) return;
    int w = t / (16 * 2401);
    int r = t - w * (16 * 2401);
    int h = r / 2401;
    int e = r - h * 2401;
    int n = e / 49;
    int m = e - n * 49;
    int di = n / 7 - m / 7 + 6;
    int dj = (n % 7) - (m % 7) + 6;
    int idx = di * 6 + dj;
    g_bm[t] = table[idx * 16 + h] + mask[w * 2401 + e];
}

// ---------------------------------------------------------------------------
// fp16 GEMM core (unchanged): block 128x128, 8 chunks of 64, 3-stage
// cp.async, ldmatrix fragment loads.

#define HGEMM_COMPUTE(sbu)                                                    \
    {                                                                         \
        _Pragma("unroll")                                                     \
        for (int ks = 0; ks < 4; ks++) {                                      \
            uint32_t af[4][4], bf[4][2];                                      \
            _Pragma("unroll")                                                 \
            for (int tm = 0; tm < 4; tm++)                                    \
                LDSM4(af[tm][0], af[tm][1], af[tm][2], af[tm][3],             \
                      (sbu) + a_off + tm * 2304 + ks * 32);                   \
            LDSM4(bf[0][0], bf[0][1], bf[1][0], bf[1][1],                     \
                  (sbu) + b_off + ks * 32);                                   \
            LDSM4(bf[2][0], bf[2][1], bf[3][0], bf[3][1],                     \
                  (sbu) + b_off + 2304 + ks * 32);                            \
            _Pragma("unroll")                                                 \
            for (int tm = 0; tm < 4; tm++)                                    \
                _Pragma("unroll")                                             \
                for (int tn = 0; tn < 4; tn++)                                \
                    MMA_F16(acc[tm][tn], af[tm], bf[tn]);                     \
        }                                                                     \
    }

#define HGEMM_PIPE(LOADM)                                                     \
    LOADM(0, 0); CP_COMMIT();                                                 \
    LOADM(1, 1); CP_COMMIT();                                                 \
    {                                                                         \
        int sl = 2, sc = 0;                                                   \
        for (int kc = 0; kc < 8; kc++) {                                      \
            CP_WAIT1();                                                       \
            __syncthreads();                                                  \
            if (kc < 6) LOADM(kc + 2, sl);                                    \
            CP_COMMIT();                                                      \
            HGEMM_COMPUTE(smem_u + sc * 36864);                               \
            sl = (sl == 2) ? 0 : sl + 1;                                      \
            sc = (sc == 2) ? 0 : sc + 1;                                      \
        }                                                                     \
    }

#define LDSM_OFFS()                                                           \
    const uint32_t a_off = 2u * ((wm * 64 + (lane & 15)) * 72 + (lane >> 4) * 8); \
    const uint32_t b_off = 18432u +                                           \
        2u * ((wn * 32 + (lane >> 4) * 8 + (lane & 7)) * 72 + ((lane >> 3) & 1) * 8);

// QKV GEMM: C[M,1536] -> q/k packed [b][h][49][32]; v transposed [b][h][32][64]
__global__ __launch_bounds__(256) void gemm_qkv_h() {
    extern __shared__ __align__(16) char smem[];
    const int tid  = threadIdx.x;
    const int lane = tid & 31, warp = tid >> 5;
    const int wm = warp >> 2, wn = warp & 3;
    const int m0 = blockIdx.y << 7;
    const int n0 = blockIdx.x << 7;
    const uint32_t smem_u = (uint32_t)__cvta_generic_to_shared(smem);

    const int r0  = tid >> 3;             // 0..31
    const int c16 = tid & 7;              // 16B segment within 128B row
    const __half* a_src = g_xh  + (long)(m0 + r0) * 512 + c16 * 8;
    const __half* b_src = g_wth + (long)(n0 + r0) * 512 + c16 * 8;
    const uint32_t a_dst = smem_u + r0 * 144 + c16 * 16;
    const uint32_t b_dst = a_dst + 18432;

#define QKV_HLOAD(kc, s)                                                       \
    {                                                                          \
        const __half* ap = a_src + (kc) * 64;                                  \
        uint32_t ad = a_dst + (s) * 36864;                                     \
        _Pragma("unroll")                                                      \
        for (int i = 0; i < 4; i++)                                            \
            cp_async16(ad + i * 4608, ap + i * 16384);                         \
        const __half* bp = b_src + (kc) * 64;                                  \
        uint32_t bd = b_dst + (s) * 36864;                                     \
        _Pragma("unroll")                                                      \
        for (int i = 0; i < 4; i++)                                            \
            cp_async16(bd + i * 4608, bp + i * 16384);                         \
    }

    float acc[4][4][4] = {};
    LDSM_OFFS();

    HGEMM_PIPE(QKV_HLOAD)

    // Epilogue: q/k -> [b][h][49][32]; v -> transposed [b][h][32][64]
#pragma unroll
    for (int tm = 0; tm < 4; tm++) {
        int r1 = m0 + wm * 64 + tm * 16 + (lane >> 2);
        int r2 = r1 + 8;
        int b1 = r1 / 49, n1 = r1 - b1 * 49;
        int b2 = r2 / 49, n2 = r2 - b2 * 49;
#pragma unroll
        for (int tn = 0; tn < 4; tn++) {
            int cidx = n0 + wn * 32 + tn * 8 + (lane & 3) * 2;
            int s  = cidx >> 9;
            int rh = cidx & 511;
            int hh = rh >> 5;
            int d  = rh & 31;
            float bb0 = g_bvec[cidx], bb1 = g_bvec[cidx + 1];
            __half2 v1 = __floats2half2_rn(acc[tm][tn][0] + bb0, acc[tm][tn][1] + bb1);
            __half2 v2 = __floats2half2_rn(acc[tm][tn][2] + bb0, acc[tm][tn][3] + bb1);
            if (s == 2) {
                __half* vt1 = g_vt + ((long)(b1 * 16 + hh) * 32 + d) * 64;
                vt1[n1]      = __low2half(v1);
                vt1[64 + n1] = __high2half(v1);
                __half* vt2 = g_vt + ((long)(b2 * 16 + hh) * 32 + d) * 64;
                vt2[n2]      = __low2half(v2);
                vt2[64 + n2] = __high2half(v2);
            } else {
                __half* dst = (s == 0) ? g_qh : g_kh;
                *(__half2*)(dst + ((long)(b1 * 16 + hh) * 49 + n1) * 32 + d) = v1;
                *(__half2*)(dst + ((long)(b2 * 16 + hh) * 49 + n2) * 32 + d) = v2;
            }
        }
    }
}

// ---------------------------------------------------------------------------
// Attention on tensor cores. 128 threads per (b,h); warp w owns S rows
// 16w..16w+15 (rows/cols padded to 64). P kept in registers (C-frag == A-frag).
__global__ __launch_bounds__(128) void attn_kernel() {
    const int h = blockIdx.x;
    const int b = blockIdx.y;
    const int w = b & 63;
    const int tid  = threadIdx.x;
    const int lane = tid & 31, wid = tid >> 5;

    __shared__ __align__(16) __half sq[64][40];
    __shared__ __align__(16) __half sk[64][40];
    __shared__ __align__(16) __half svt[32][72];

    const long tb = (long)(b * 16 + h) * 1568;        // 49*32
    const long vb = (long)(b * 16 + h) * 2048;        // 32*64
    {
        const uint4 z = {0u, 0u, 0u, 0u};
#pragma unroll
        for (int it = 0; it < 2; it++) {
            int s = tid + it * 128;                   // 0..255 = 64 rows x 4 seg
            int row = s >> 2, seg = (s & 3) << 3;
            uint4 vq = z, vk = z;
            if (row < 49) {
                vq = *(const uint4*)(g_qh + tb + row * 32 + seg);
                vk = *(const uint4*)(g_kh + tb + row * 32 + seg);
            }
            *(uint4*)&sq[row][seg] = vq;
            *(uint4*)&sk[row][seg] = vk;
        }
#pragma unroll
        for (int it = 0; it < 2; it++) {
            int s = tid + it * 128;                   // 0..255 = 32 rows x 8 seg
            int d = s >> 3, seg = (s & 7) << 3;
            *(uint4*)&svt[d][seg] = *(const uint4*)(g_vt + vb + d * 64 + seg);
        }
    }
    __syncthreads();

    const uint32_t squ = (uint32_t)__cvta_generic_to_shared(&sq[0][0]);
    const uint32_t sku = (uint32_t)__cvta_generic_to_shared(&sk[0][0]);
    const uint32_t svu = (uint32_t)__cvta_generic_to_shared(&svt[0][0]);

    const uint32_t a_addr = squ + 2u * ((wid * 16 + (lane & 15)) * 40 + (lane >> 4) * 8);
    const uint32_t brow = (lane >> 4) * 8 + (lane & 7);
    const uint32_t bks  = ((lane >> 3) & 1) * 8;

    // ---- QK^T: S[16][64] per warp (8 n8-tiles) ----
    float sacc[8][4];
#pragma unroll
    for (int i = 0; i < 8; i++)
        sacc[i][0] = sacc[i][1] = sacc[i][2] = sacc[i][3] = 0.f;

#pragma unroll
    for (int ks = 0; ks < 2; ks++) {
        uint32_t af[4];
        LDSM4(af[0], af[1], af[2], af[3], a_addr + ks * 32);
#pragma unroll
        for (int nb = 0; nb < 4; nb++) {
            uint32_t bfa[2], bfb[2];
            LDSM4(bfa[0], bfa[1], bfb[0], bfb[1],
                  sku + 2u * ((nb * 16 + brow) * 40 + bks) + ks * 32);
            MMA_F16(sacc[2 * nb],     af, bfa);
            MMA_F16(sacc[2 * nb + 1], af, bfb);
        }
    }

    // ---- bias+mask, exp (no max pass; pads -> -1e4 -> 0), row sums ----
    const int rlo  = wid * 16 + (lane >> 2);
    const int rhi  = rlo + 8;
    const int col0 = (lane & 3) * 2;
    const float* bmp = g_bm + (w * 16 + h) * 2401;
    float rsl = 0.f, rsh = 0.f;
    uint32_t pe[8][2];
#pragma unroll
    for (int n8 = 0; n8 < 8; n8++) {
        int c = n8 * 8 + col0;
        float b00 = (rlo < 49 && c < 49)     ? bmp[rlo * 49 + c]     : -1e4f;
        float b01 = (rlo < 49 && c + 1 < 49) ? bmp[rlo * 49 + c + 1] : -1e4f;
        float b10 = (rhi < 49 && c < 49)     ? bmp[rhi * 49 + c]     : -1e4f;
        float b11 = (rhi < 49 && c + 1 < 49) ? bmp[rhi * 49 + c + 1] : -1e4f;
        float e0 = __expf(sacc[n8][0] + b00);
        float e1 = __expf(sacc[n8][1] + b01);
        float e2 = __expf(sacc[n8][2] + b10);
        float e3 = __expf(sacc[n8][3] + b11);
        rsl += e0 + e1;
        rsh += e2 + e3;
        __half2 p0 = __floats2half2_rn(e0 * 0.0625f, e1 * 0.0625f);  // /16: fp16 range
        __half2 p1 = __floats2half2_rn(e2 * 0.0625f, e3 * 0.0625f);
        pe[n8][0] = *(uint32_t*)&p0;
        pe[n8][1] = *(uint32_t*)&p1;
    }
    rsl += __shfl_xor_sync(0xffffffffu, rsl, 1);
    rsl += __shfl_xor_sync(0xffffffffu, rsl, 2);
    rsh += __shfl_xor_sync(0xffffffffu, rsh, 1);
    rsh += __shfl_xor_sync(0xffffffffu, rsh, 2);
    const float sil = 16.f / rsl;
    const float sih = 16.f / rsh;

    // ---- PV: O[16][32] per warp; A = P fragments (C-frag == A-frag map) ----
    float oacc[4][4];
#pragma unroll
    for (int i = 0; i < 4; i++)
        oacc[i][0] = oacc[i][1] = oacc[i][2] = oacc[i][3] = 0.f;

#pragma unroll
    for (int ks = 0; ks < 4; ks++) {
        uint32_t af2[4] = { pe[2 * ks][0], pe[2 * ks][1],
                            pe[2 * ks + 1][0], pe[2 * ks + 1][1] };
#pragma unroll
        for (int db = 0; db < 2; db++) {
            uint32_t bfa[2], bfb[2];
            LDSM4(bfa[0], bfa[1], bfb[0], bfb[1],
                  svu + 2u * ((db * 16 + brow) * 72 + bks) + ks * 32);
            MMA_F16(oacc[2 * db],     af2, bfa);
            MMA_F16(oacc[2 * db + 1], af2, bfb);
        }
    }

    // ---- store O (guarded rows) ----
    __half* ob = g_aoh + (long)b * 25088 + h * 32;
#pragma unroll
    for (int dn = 0; dn < 4; dn++) {
        int d = dn * 8 + col0;
        if (rlo < 49)
            *(__half2*)(ob + (long)rlo * 512 + d) =
                __floats2half2_rn(oacc[dn][0] * sil, oacc[dn][1] * sil);
        if (rhi < 49)
            *(__half2*)(ob + (long)rhi * 512 + d) =
                __floats2half2_rn(oacc[dn][2] * sih, oacc[dn][3] * sih);
    }
}

// ---------------------------------------------------------------------------
// Proj GEMM (fp16 HMMA + ldmatrix, unchanged): Y = g_aoh @ g_pwt^T + proj_b.
__global__ __launch_bounds__(256) void gemm_proj_h(const float* __restrict__ pb,
                                                   float* __restrict__ out) {
    extern __shared__ __align__(16) char smem[];
    float* smf = (float*)smem;
    const int tid  = threadIdx.x;
    const int lane = tid & 31, warp = tid >> 5;
    const int wm = warp >> 2, wn = warp & 3;
    const int m0 = blockIdx.y << 7;
    const int n0 = blockIdx.x << 7;
    const uint32_t smem_u = (uint32_t)__cvta_generic_to_shared(smem);

    const int r0  = tid >> 3;
    const int c16 = tid & 7;
    const __half* a_src = g_aoh + (long)(m0 + r0) * 512 + c16 * 8;
    const __half* b_src = g_pwt + (long)(n0 + r0) * 512 + c16 * 8;
    const uint32_t a_dst = smem_u + r0 * 144 + c16 * 16;
    const uint32_t b_dst = a_dst + 18432;

#define PROJ_HLOAD(kc, s)                                                      \
    {                                                                          \
        const __half* ap = a_src + (kc) * 64;                                  \
        uint32_t ad = a_dst + (s) * 36864;                                     \
        _Pragma("unroll")                                                      \
        for (int i = 0; i < 4; i++)                                            \
            cp_async16(ad + i * 4608, ap + i * 16384);                         \
        const __half* bp = b_src + (kc) * 64;                                  \
        uint32_t bd = b_dst + (s) * 36864;                                     \
        _Pragma("unroll")                                                      \
        for (int i = 0; i < 4; i++)                                            \
            cp_async16(bd + i * 4608, bp + i * 16384);                         \
    }

    float acc[4][4][4] = {};
    LDSM_OFFS();

    HGEMM_PIPE(PROJ_HLOAD)

    // Transposed epilogue via smem staging, two 64-column halves.
    float* stg = smf;                      // [128][66]
    const int r_l  = tid & 127;
    int rowg = m0 + r_l;
    int ob_b = rowg / 49;
    int ob_n = rowg - ob_b * 49;
    float* obase = out + (long)ob_b * 25088 + ob_n;
    const int ccb = tid >> 7;

    for (int half = 0; half < 2; half++) {
        __syncthreads();
        if ((wn >> 1) == half) {
#pragma unroll
            for (int tm = 0; tm < 4; tm++) {
                int rl = wm * 64 + tm * 16 + (lane >> 2);
#pragma unroll
                for (int tn = 0; tn < 4; tn++) {
                    int cl = (wn & 1) * 32 + tn * 8 + (lane & 3) * 2;
                    int cg = n0 + half * 64 + cl;
                    float b0 = pb[cg], b1 = pb[cg + 1];
                    stg[rl * 66 + cl]           = acc[tm][tn][0] + b0;
                    stg[rl * 66 + cl + 1]       = acc[tm][tn][1] + b1;
                    stg[(rl + 8) * 66 + cl]     = acc[tm][tn][2] + b0;
                    stg[(rl + 8) * 66 + cl + 1] = acc[tm][tn][3] + b1;
                }
            }
        }
        __syncthreads();
#pragma unroll
        for (int i = 0; i < 32; i++) {
            int cc = ccb + 2 * i;
            int ch = n0 + half * 64 + cc;
            obase[(long)ch * 49] = stg[r_l * 66 + cc];
        }
    }
}

// ---------------------------------------------------------------------------
extern "C" void kernel_launch(void* const* d_in, const int* in_sizes, int n_in,
                              void* d_out, int out_size) {
    const float *x = nullptr, *mask = nullptr, *table = nullptr;
    const float *qw = nullptr, *qb = nullptr, *pw = nullptr, *pb = nullptr;
    for (int i = 0; i < n_in; i++) {
        const float* p = (const float*)d_in[i];
        switch (in_sizes[i]) {
            case 51380224: x = p; break;
            case 153664:   mask = p; break;
            case 2704:     table = p; break;
            case 786432:   qw = p; break;
            case 1536:     qb = p; break;
            case 262144:   pw = p; break;
            case 512:      pb = p; break;
        }
    }
    float* out = (float*)d_out;

    const int gemm_smem = 110592;   // 3 stages * 36864 B
    cudaFuncSetAttribute(gemm_qkv_h,  cudaFuncAttributeMaxDynamicSharedMemorySize, gemm_smem);
    cudaFuncSetAttribute(gemm_proj_h, cudaFuncAttributeMaxDynamicSharedMemorySize, gemm_smem);

    prep_w_kernel<<<(512 * 1536 + 255) / 256, 256>>>(qw, qb, pw);
    prep_bm_kernel<<<(64 * 16 * 2401 + 255) / 256, 256>>>(mask, table);
    prep_xt_kernel<<<dim3(4, 2048), 256>>>(x);
    gemm_qkv_h<<<dim3(12, 784), 256, gemm_smem>>>();
    attn_kernel<<<dim3(16, 2048), 128>>>();
    gemm_proj_h<<<dim3(4, 784), 256, gemm_smem>>>(pb, out);
}